// round 3
// baseline (speedup 1.0000x reference)
#include <cuda_runtime.h>
#include <cuda_bf16.h>
#include <math.h>
#include <stdint.h>

// ---------------- Problem constants ----------------
#define BB      2
#define LL      4096
#define DMODEL  1024
#define DSSM    2048
#define DSTATE  128
#define DCONV   4
#define NH      32
#define HD      64
#define CONVDIM (DSSM + 2*DSTATE)          // 2304
#define DPROJ   (2*DSSM + 2*DSTATE + NH)   // 4384
#define EPSV    1e-5f

#define ROWS    (BB*LL)                    // 8192

// ---------------- Scratch (static device arrays; no allocation) ----------------
__device__ float g_zxbcdt[(size_t)ROWS * DPROJ];   // in-proj output
__device__ float g_xbc[(size_t)ROWS * CONVDIM];    // conv+silu output
__device__ float g_dt[(size_t)ROWS * NH];          // softplus(dt)
__device__ float g_dA[(size_t)ROWS * NH];          // exp(dt*A)
__device__ float g_y[(size_t)ROWS * DSSM];         // scan output -> gated/normed in place

// ---------------- helpers ----------------
__device__ __forceinline__ float silu_f(float x) {
    return x / (1.0f + expf(-x));
}

__device__ __forceinline__ float to_tf32(float x) {
    uint32_t u;
    asm("cvt.rna.tf32.f32 %0, %1;" : "=r"(u) : "f"(x));
    return __uint_as_float(u);
}

// ---------------- tf32 tensor-core GEMM: C[m,n] = sum_k A[m,k]*B[n,k] (NT) ----------------
// BM=BN=128, BK=16, 256 threads (8 warps), warp tile 32x64 via m16n8k8 tf32 mma.
// M % 128 == 0, K % 16 == 0; N ragged ok (N % 2 == 0).
__global__ __launch_bounds__(256) void tf32gemm_nt_kernel(
    const float* __restrict__ A, const float* __restrict__ B, float* __restrict__ C,
    int M, int N, int K)
{
    __shared__ float As[128][20];   // [m][k], pad 20 -> conflict-free frag reads
    __shared__ float Bs[128][20];   // [n][k]

    const int tid  = threadIdx.x;
    const int warp = tid >> 5;
    const int lane = tid & 31;
    const int g    = lane >> 2;     // 0..7
    const int t4   = lane & 3;      // 0..3
    const int wm   = (warp >> 1) * 32;  // warp row offset (4 warps in M)
    const int wn   = (warp & 1) * 64;   // warp col offset (2 warps in N)
    const int m0   = blockIdx.y * 128;
    const int n0   = blockIdx.x * 128;

    float d[2][8][4];
#pragma unroll
    for (int i = 0; i < 2; i++)
#pragma unroll
        for (int j = 0; j < 8; j++)
#pragma unroll
            for (int v = 0; v < 4; v++) d[i][j][v] = 0.0f;

    // staging indices: 512 float4 loads per tile-pair; 2 per thread
    const int srow = tid >> 2;          // 0..63 (row for r=0), +64 for r=1
    const int skq  = (tid & 3) * 4;     // 0,4,8,12

    for (int k0 = 0; k0 < K; k0 += 16) {
#pragma unroll
        for (int r = 0; r < 2; r++) {
            int row = srow + r * 64;
            // A
            float4 va = *(const float4*)&A[(size_t)(m0 + row) * K + k0 + skq];
            va.x = to_tf32(va.x); va.y = to_tf32(va.y);
            va.z = to_tf32(va.z); va.w = to_tf32(va.w);
            *(float4*)&As[row][skq] = va;
            // B (ragged N guard)
            int nrow = n0 + row;
            float4 vb = make_float4(0.f, 0.f, 0.f, 0.f);
            if (nrow < N) vb = *(const float4*)&B[(size_t)nrow * K + k0 + skq];
            vb.x = to_tf32(vb.x); vb.y = to_tf32(vb.y);
            vb.z = to_tf32(vb.z); vb.w = to_tf32(vb.w);
            *(float4*)&Bs[row][skq] = vb;
        }
        __syncthreads();

#pragma unroll
        for (int s = 0; s < 2; s++) {
            const int kk = 8 * s;
            uint32_t af[2][4];
#pragma unroll
            for (int mt = 0; mt < 2; mt++) {
                const int mr = wm + mt * 16;
                af[mt][0] = __float_as_uint(As[mr + g    ][kk + t4    ]);
                af[mt][1] = __float_as_uint(As[mr + g + 8][kk + t4    ]);
                af[mt][2] = __float_as_uint(As[mr + g    ][kk + t4 + 4]);
                af[mt][3] = __float_as_uint(As[mr + g + 8][kk + t4 + 4]);
            }
            uint32_t bf[8][2];
#pragma unroll
            for (int nt = 0; nt < 8; nt++) {
                const int nr = wn + nt * 8 + g;
                bf[nt][0] = __float_as_uint(Bs[nr][kk + t4    ]);
                bf[nt][1] = __float_as_uint(Bs[nr][kk + t4 + 4]);
            }
#pragma unroll
            for (int mt = 0; mt < 2; mt++) {
#pragma unroll
                for (int nt = 0; nt < 8; nt++) {
                    asm volatile(
                        "mma.sync.aligned.m16n8k8.row.col.f32.tf32.tf32.f32 "
                        "{%0,%1,%2,%3}, {%4,%5,%6,%7}, {%8,%9}, {%0,%1,%2,%3};"
                        : "+f"(d[mt][nt][0]), "+f"(d[mt][nt][1]),
                          "+f"(d[mt][nt][2]), "+f"(d[mt][nt][3])
                        : "r"(af[mt][0]), "r"(af[mt][1]), "r"(af[mt][2]), "r"(af[mt][3]),
                          "r"(bf[nt][0]), "r"(bf[nt][1]));
                }
            }
        }
        __syncthreads();
    }

    // epilogue: d0/d1 -> (row g, cols t4*2, t4*2+1); d2/d3 -> row g+8
#pragma unroll
    for (int mt = 0; mt < 2; mt++) {
        const int mrow = m0 + wm + mt * 16;
#pragma unroll
        for (int nt = 0; nt < 8; nt++) {
            const int ncol = n0 + wn + nt * 8 + t4 * 2;
            if (ncol < N) {
                *(float2*)&C[(size_t)(mrow + g    ) * N + ncol] =
                    make_float2(d[mt][nt][0], d[mt][nt][1]);
                *(float2*)&C[(size_t)(mrow + g + 8) * N + ncol] =
                    make_float2(d[mt][nt][2], d[mt][nt][3]);
            }
        }
    }
}

// ---------------- conv1d (width 4, causal) + bias + SiLU ----------------
__global__ __launch_bounds__(256) void conv_silu_kernel(
    const float* __restrict__ conv_w, const float* __restrict__ conv_b)
{
    size_t idx = (size_t)blockIdx.x * blockDim.x + threadIdx.x;
    if (idx >= (size_t)ROWS * CONVDIM) return;
    int c = (int)(idx % CONVDIM);
    size_t bt = idx / CONVDIM;
    int t = (int)(bt % LL);
    size_t brow0 = (bt - t); // (b*L) base row

    float accv = conv_b[c];
#pragma unroll
    for (int w = 0; w < DCONV; w++) {
        int ts = t - (DCONV - 1) + w;
        if (ts >= 0) {
            accv = fmaf(g_zxbcdt[(brow0 + ts) * (size_t)DPROJ + DSSM + c],
                        conv_w[c * DCONV + w], accv);
        }
    }
    g_xbc[idx] = silu_f(accv);
}

// ---------------- dt softplus + dA precompute ----------------
__global__ __launch_bounds__(256) void dt_kernel(
    const float* __restrict__ dt_bias, const float* __restrict__ A_log)
{
    int idx = blockIdx.x * blockDim.x + threadIdx.x;
    if (idx >= ROWS * NH) return;
    int h = idx % NH;
    int r = idx / NH;
    float raw = g_zxbcdt[(size_t)r * DPROJ + DSSM + CONVDIM + h] + dt_bias[h];
    float dt = (raw > 20.0f) ? raw : log1pf(expf(raw));
    float Aneg = -expf(A_log[h]);
    g_dt[idx] = dt;
    g_dA[idx] = expf(dt * Aneg);
}

// ---------------- selective scan ----------------
// 128 CTAs: (b, h, p-half). 256 threads: warp w -> 4 p's, lane -> 4 n's. State 4x4 regs.
__global__ __launch_bounds__(256) void scan_kernel(const float* __restrict__ Dp)
{
    const int blk = blockIdx.x;        // 0..127
    const int b = blk >> 6;
    const int hh = blk & 63;
    const int h = hh >> 1;
    const int p_base = (hh & 1) * 32;

    const int tid = threadIdx.x;
    const int w = tid >> 5;
    const int lane = tid & 31;
    const int p0 = p_base + w * 4;

    __shared__ float4 sB[2][32];
    __shared__ float4 sC[2][32];
    __shared__ float4 sx[2][8];
    __shared__ float sdt[2], sdA[2];

    float hs[4][4];
#pragma unroll
    for (int i = 0; i < 4; i++)
#pragma unroll
        for (int j = 0; j < 4; j++) hs[i][j] = 0.0f;

    const float Dh = Dp[h];
    const float* base = g_xbc + (size_t)b * LL * CONVDIM;
    const size_t dtbase = (size_t)b * LL * NH + h;
    float* yout = g_y + (size_t)b * LL * DSSM + h * HD;

    // stage 0 preload
    {
        const float* rb = base;
        if (tid < 32)       sB[0][tid]      = *(const float4*)(rb + DSSM + tid * 4);
        else if (tid < 64)  sC[0][tid - 32] = *(const float4*)(rb + DSSM + DSTATE + (tid - 32) * 4);
        else if (tid < 72)  sx[0][tid - 64] = *(const float4*)(rb + h * HD + p_base + (tid - 64) * 4);
        else if (tid == 72) sdt[0] = g_dt[dtbase];
        else if (tid == 73) sdA[0] = g_dA[dtbase];
    }

    for (int t = 0; t < LL; t++) {
        __syncthreads();
        const int cur = t & 1;
        if (t + 1 < LL) {
            const float* rb = base + (size_t)(t + 1) * CONVDIM;
            const int nxt = cur ^ 1;
            if (tid < 32)       sB[nxt][tid]      = *(const float4*)(rb + DSSM + tid * 4);
            else if (tid < 64)  sC[nxt][tid - 32] = *(const float4*)(rb + DSSM + DSTATE + (tid - 32) * 4);
            else if (tid < 72)  sx[nxt][tid - 64] = *(const float4*)(rb + h * HD + p_base + (tid - 64) * 4);
            else if (tid == 72) sdt[nxt] = g_dt[dtbase + (size_t)(t + 1) * NH];
            else if (tid == 73) sdA[nxt] = g_dA[dtbase + (size_t)(t + 1) * NH];
        }

        const float dtv = sdt[cur];
        const float dAv = sdA[cur];
        const float4 Bv = sB[cur][lane];
        const float4 Cv = sC[cur][lane];
        const float4 xv = sx[cur][w];

        const float bb[4] = {Bv.x, Bv.y, Bv.z, Bv.w};
        const float cc[4] = {Cv.x, Cv.y, Cv.z, Cv.w};
        const float xx[4] = {xv.x, xv.y, xv.z, xv.w};

        float acc[4] = {0.f, 0.f, 0.f, 0.f};
#pragma unroll
        for (int i = 0; i < 4; i++) {
            const float dtx = dtv * xx[i];
#pragma unroll
            for (int j = 0; j < 4; j++) {
                hs[i][j] = fmaf(hs[i][j], dAv, dtx * bb[j]);
                acc[i] = fmaf(hs[i][j], cc[j], acc[i]);
            }
        }
        // reduce each acc over all 32 lanes (n dimension)
#pragma unroll
        for (int i = 0; i < 4; i++) {
            float a = acc[i];
            a += __shfl_xor_sync(0xffffffffu, a, 16);
            a += __shfl_xor_sync(0xffffffffu, a, 8);
            a += __shfl_xor_sync(0xffffffffu, a, 4);
            a += __shfl_xor_sync(0xffffffffu, a, 2);
            a += __shfl_xor_sync(0xffffffffu, a, 1);
            acc[i] = a;
        }
        if (lane < 4) {
            float res = (lane == 0) ? acc[0] : (lane == 1) ? acc[1] : (lane == 2) ? acc[2] : acc[3];
            float xval = (lane == 0) ? xv.x : (lane == 1) ? xv.y : (lane == 2) ? xv.z : xv.w;
            yout[(size_t)t * DSSM + p0 + lane] = fmaf(Dh, xval, res);
        }
    }
}

// ---------------- gate (silu(z)) + RMSNorm (in place on g_y) ----------------
__global__ __launch_bounds__(256) void gate_rmsnorm_kernel(const float* __restrict__ norm_w)
{
    const int row = blockIdx.x;      // 0..8191
    const int tid = threadIdx.x;
    const int w = tid >> 5, lane = tid & 31;

    float vals[8];
    float ss = 0.f;
#pragma unroll
    for (int i = 0; i < 8; i++) {
        int e = i * 256 + tid;
        float z = g_zxbcdt[(size_t)row * DPROJ + e];
        float yv = g_y[(size_t)row * DSSM + e];
        float g = yv * silu_f(z);
        vals[i] = g;
        ss = fmaf(g, g, ss);
    }
    ss += __shfl_xor_sync(0xffffffffu, ss, 16);
    ss += __shfl_xor_sync(0xffffffffu, ss, 8);
    ss += __shfl_xor_sync(0xffffffffu, ss, 4);
    ss += __shfl_xor_sync(0xffffffffu, ss, 2);
    ss += __shfl_xor_sync(0xffffffffu, ss, 1);

    __shared__ float red[8];
    __shared__ float sscale;
    if (lane == 0) red[w] = ss;
    __syncthreads();
    if (tid == 0) {
        float s = 0.f;
#pragma unroll
        for (int k = 0; k < 8; k++) s += red[k];
        sscale = rsqrtf(s / (float)DSSM + EPSV);
    }
    __syncthreads();
    const float scale = sscale;
#pragma unroll
    for (int i = 0; i < 8; i++) {
        int e = i * 256 + tid;
        g_y[(size_t)row * DSSM + e] = vals[i] * scale * norm_w[e];
    }
}

// ---------------- entry ----------------
extern "C" void kernel_launch(void* const* d_in, const int* in_sizes, int n_in,
                              void* d_out, int out_size)
{
    const float* u       = (const float*)d_in[0];  // [2,4096,1024]
    const float* W_in    = (const float*)d_in[1];  // [4384,1024]
    const float* conv_w  = (const float*)d_in[2];  // [2304,4]
    const float* conv_b  = (const float*)d_in[3];  // [2304]
    const float* dt_bias = (const float*)d_in[4];  // [32]
    const float* A_log   = (const float*)d_in[5];  // [32]
    const float* Dp      = (const float*)d_in[6];  // [32]
    const float* norm_w  = (const float*)d_in[7];  // [2048]
    const float* W_out   = (const float*)d_in[8];  // [1024,2048]
    float* out = (float*)d_out;                    // [2,4096,1024]

    float* zx;  cudaGetSymbolAddress((void**)&zx,  g_zxbcdt);
    float* gy;  cudaGetSymbolAddress((void**)&gy,  g_y);

    // 1) in-projection: zxbcdt = u @ W_in^T   (tf32 tensor cores)
    {
        dim3 grid((DPROJ + 127) / 128, ROWS / 128);
        tf32gemm_nt_kernel<<<grid, 256>>>(u, W_in, zx, ROWS, DPROJ, DMODEL);
    }
    // 2) conv + silu
    {
        size_t total = (size_t)ROWS * CONVDIM;
        conv_silu_kernel<<<(unsigned)((total + 255) / 256), 256>>>(conv_w, conv_b);
    }
    // 3) dt softplus + dA
    dt_kernel<<<(ROWS * NH + 255) / 256, 256>>>(dt_bias, A_log);
    // 4) selective scan
    scan_kernel<<<128, 256>>>(Dp);
    // 5) gate + rmsnorm (in place on g_y)
    gate_rmsnorm_kernel<<<ROWS, 256>>>(norm_w);
    // 6) out-projection: out = g @ W_out^T   (tf32 tensor cores)
    {
        dim3 grid(DMODEL / 128, ROWS / 128);
        tf32gemm_nt_kernel<<<grid, 256>>>(gy, W_out, out, ROWS, DMODEL, DSSM);
    }
}

// round 5
// speedup vs baseline: 1.4069x; 1.4069x over previous
#include <cuda_runtime.h>
#include <cuda_bf16.h>
#include <math.h>
#include <stdint.h>

// ---------------- Problem constants ----------------
#define BB      2
#define LL      4096
#define DMODEL  1024
#define DSSM    2048
#define DSTATE  128
#define DCONV   4
#define NH      32
#define HD      64
#define CONVDIM (DSSM + 2*DSTATE)          // 2304
#define DPROJ   (2*DSSM + 2*DSTATE + NH)   // 4384
#define EPSV    1e-5f

#define ROWS    (BB*LL)                    // 8192

// ---------------- Scratch (static device arrays; no allocation) ----------------
__device__ float g_zxbcdt[(size_t)ROWS * DPROJ];   // in-proj output
__device__ float g_xbc[(size_t)ROWS * CONVDIM];    // conv+silu output
__device__ float g_dt[(size_t)ROWS * NH];          // softplus(dt)
__device__ float g_dA[(size_t)ROWS * NH];          // exp(dt*A)
__device__ float g_y[(size_t)ROWS * DSSM];         // scan output -> gated/normed in place

// ---------------- helpers ----------------
__device__ __forceinline__ float silu_f(float x) {
    return x / (1.0f + expf(-x));
}

__device__ __forceinline__ float to_tf32(float x) {
    uint32_t u;
    asm("cvt.rna.tf32.f32 %0, %1;" : "=r"(u) : "f"(x));
    return __uint_as_float(u);
}

__device__ __forceinline__ void ldsm4(uint32_t &r0, uint32_t &r1, uint32_t &r2, uint32_t &r3,
                                      uint32_t saddr) {
    asm volatile("ldmatrix.sync.aligned.m8n8.x4.shared.b16 {%0,%1,%2,%3}, [%4];"
                 : "=r"(r0), "=r"(r1), "=r"(r2), "=r"(r3)
                 : "r"(saddr));
}

// ---------------- tf32 tensor-core GEMM: C[m,n] = sum_k A[m,k]*B[n,k] (NT) ----------------
// BM=BN=128, BK=16, 256 threads (8 warps), warp tile 32x64 via m16n8k8 tf32 mma.
// Fragment loads via ldmatrix.x4 (conflict-free with row stride 20).
// M % 128 == 0, K % 16 == 0; N ragged ok (N % 2 == 0).
__global__ __launch_bounds__(256) void tf32gemm_nt_kernel(
    const float* __restrict__ A, const float* __restrict__ B, float* __restrict__ C,
    int M, int N, int K)
{
    __shared__ __align__(16) float As[128][20];   // [m][k], stride 20 -> LDSM conflict-free
    __shared__ __align__(16) float Bs[128][20];   // [n][k]

    const int tid  = threadIdx.x;
    const int warp = tid >> 5;
    const int lane = tid & 31;
    const int t4   = lane & 3;      // 0..3 (used by epilogue)
    const int g    = lane >> 2;     // 0..7 (epilogue row)
    const int wm   = (warp >> 1) * 32;  // warp row offset (4 warps in M)
    const int wn   = (warp & 1) * 64;   // warp col offset (2 warps in N)
    const int m0   = blockIdx.y * 128;
    const int n0   = blockIdx.x * 128;

    // ldmatrix lane -> row address decomposition
    const int lm  = lane >> 3;      // matrix index 0..3
    const int lr  = lane & 7;       // row within matrix
    const int arow_off = (lm & 1) * 8 + lr;     // A: row within 16-row block
    const int acol_off = (lm >> 1) * 4;         // A: k offset within 8
    const int brow_off = (lm >> 1) * 8 + lr;    // B: row within 16-row (nt pair) block
    const int bcol_off = (lm & 1) * 4;          // B: k offset within 8

    const uint32_t as_base = (uint32_t)__cvta_generic_to_shared(&As[0][0]);
    const uint32_t bs_base = (uint32_t)__cvta_generic_to_shared(&Bs[0][0]);

    float d[2][8][4];
#pragma unroll
    for (int i = 0; i < 2; i++)
#pragma unroll
        for (int j = 0; j < 8; j++)
#pragma unroll
            for (int v = 0; v < 4; v++) d[i][j][v] = 0.0f;

    // staging indices: 512 float4 loads per tile-pair; 2 per thread
    const int srow = tid >> 2;          // 0..63 (row for r=0), +64 for r=1
    const int skq  = (tid & 3) * 4;     // 0,4,8,12

    for (int k0 = 0; k0 < K; k0 += 16) {
#pragma unroll
        for (int r = 0; r < 2; r++) {
            int row = srow + r * 64;
            // A
            float4 va = *(const float4*)&A[(size_t)(m0 + row) * K + k0 + skq];
            va.x = to_tf32(va.x); va.y = to_tf32(va.y);
            va.z = to_tf32(va.z); va.w = to_tf32(va.w);
            *(float4*)&As[row][skq] = va;
            // B (ragged N guard)
            int nrow = n0 + row;
            float4 vb = make_float4(0.f, 0.f, 0.f, 0.f);
            if (nrow < N) vb = *(const float4*)&B[(size_t)nrow * K + k0 + skq];
            vb.x = to_tf32(vb.x); vb.y = to_tf32(vb.y);
            vb.z = to_tf32(vb.z); vb.w = to_tf32(vb.w);
            *(float4*)&Bs[row][skq] = vb;
        }
        __syncthreads();

#pragma unroll
        for (int s = 0; s < 2; s++) {
            const int kk = 8 * s;
            // A fragments: one ldmatrix.x4 per mt
            uint32_t af[2][4];
#pragma unroll
            for (int mt = 0; mt < 2; mt++) {
                uint32_t addr = as_base +
                    (uint32_t)(((wm + mt * 16 + arow_off) * 20 + kk + acol_off) * 4);
                ldsm4(af[mt][0], af[mt][1], af[mt][2], af[mt][3], addr);
            }
            // B fragments: one ldmatrix.x4 per nt-pair
            uint32_t bf[8][2];
#pragma unroll
            for (int ntp = 0; ntp < 4; ntp++) {
                uint32_t q0, q1, q2, q3;
                uint32_t addr = bs_base +
                    (uint32_t)(((wn + ntp * 16 + brow_off) * 20 + kk + bcol_off) * 4);
                ldsm4(q0, q1, q2, q3, addr);
                bf[2 * ntp][0] = q0;  bf[2 * ntp][1] = q1;
                bf[2 * ntp + 1][0] = q2;  bf[2 * ntp + 1][1] = q3;
            }
#pragma unroll
            for (int mt = 0; mt < 2; mt++) {
#pragma unroll
                for (int nt = 0; nt < 8; nt++) {
                    asm volatile(
                        "mma.sync.aligned.m16n8k8.row.col.f32.tf32.tf32.f32 "
                        "{%0,%1,%2,%3}, {%4,%5,%6,%7}, {%8,%9}, {%0,%1,%2,%3};"
                        : "+f"(d[mt][nt][0]), "+f"(d[mt][nt][1]),
                          "+f"(d[mt][nt][2]), "+f"(d[mt][nt][3])
                        : "r"(af[mt][0]), "r"(af[mt][1]), "r"(af[mt][2]), "r"(af[mt][3]),
                          "r"(bf[nt][0]), "r"(bf[nt][1]));
                }
            }
        }
        __syncthreads();
    }

    // epilogue: d0/d1 -> (row g, cols t4*2, t4*2+1); d2/d3 -> row g+8
#pragma unroll
    for (int mt = 0; mt < 2; mt++) {
        const int mrow = m0 + wm + mt * 16;
#pragma unroll
        for (int nt = 0; nt < 8; nt++) {
            const int ncol = n0 + wn + nt * 8 + t4 * 2;
            if (ncol < N) {
                *(float2*)&C[(size_t)(mrow + g    ) * N + ncol] =
                    make_float2(d[mt][nt][0], d[mt][nt][1]);
                *(float2*)&C[(size_t)(mrow + g + 8) * N + ncol] =
                    make_float2(d[mt][nt][2], d[mt][nt][3]);
            }
        }
    }
}

// ---------------- conv1d (width 4, causal) + bias + SiLU ----------------
__global__ __launch_bounds__(256) void conv_silu_kernel(
    const float* __restrict__ conv_w, const float* __restrict__ conv_b)
{
    size_t idx = (size_t)blockIdx.x * blockDim.x + threadIdx.x;
    if (idx >= (size_t)ROWS * CONVDIM) return;
    int c = (int)(idx % CONVDIM);
    size_t bt = idx / CONVDIM;
    int t = (int)(bt % LL);
    size_t brow0 = (bt - t); // (b*L) base row

    float accv = conv_b[c];
#pragma unroll
    for (int w = 0; w < DCONV; w++) {
        int ts = t - (DCONV - 1) + w;
        if (ts >= 0) {
            accv = fmaf(g_zxbcdt[(brow0 + ts) * (size_t)DPROJ + DSSM + c],
                        conv_w[c * DCONV + w], accv);
        }
    }
    g_xbc[idx] = silu_f(accv);
}

// ---------------- dt softplus + dA precompute ----------------
__global__ __launch_bounds__(256) void dt_kernel(
    const float* __restrict__ dt_bias, const float* __restrict__ A_log)
{
    int idx = blockIdx.x * blockDim.x + threadIdx.x;
    if (idx >= ROWS * NH) return;
    int h = idx % NH;
    int r = idx / NH;
    float raw = g_zxbcdt[(size_t)r * DPROJ + DSSM + CONVDIM + h] + dt_bias[h];
    float dt = (raw > 20.0f) ? raw : log1pf(expf(raw));
    float Aneg = -expf(A_log[h]);
    g_dt[idx] = dt;
    g_dA[idx] = expf(dt * Aneg);
}

// ---------------- selective scan ----------------
// 128 CTAs: (b, h, p-half). 256 threads: warp w -> 4 p's, lane -> 4 n's. State 4x4 regs.
__global__ __launch_bounds__(256) void scan_kernel(const float* __restrict__ Dp)
{
    const int blk = blockIdx.x;        // 0..127
    const int b = blk >> 6;
    const int hh = blk & 63;
    const int h = hh >> 1;
    const int p_base = (hh & 1) * 32;

    const int tid = threadIdx.x;
    const int w = tid >> 5;
    const int lane = tid & 31;
    const int p0 = p_base + w * 4;

    __shared__ float4 sB[2][32];
    __shared__ float4 sC[2][32];
    __shared__ float4 sx[2][8];
    __shared__ float sdt[2], sdA[2];

    float hs[4][4];
#pragma unroll
    for (int i = 0; i < 4; i++)
#pragma unroll
        for (int j = 0; j < 4; j++) hs[i][j] = 0.0f;

    const float Dh = Dp[h];
    const float* base = g_xbc + (size_t)b * LL * CONVDIM;
    const size_t dtbase = (size_t)b * LL * NH + h;
    float* yout = g_y + (size_t)b * LL * DSSM + h * HD;

    // stage 0 preload
    {
        const float* rb = base;
        if (tid < 32)       sB[0][tid]      = *(const float4*)(rb + DSSM + tid * 4);
        else if (tid < 64)  sC[0][tid - 32] = *(const float4*)(rb + DSSM + DSTATE + (tid - 32) * 4);
        else if (tid < 72)  sx[0][tid - 64] = *(const float4*)(rb + h * HD + p_base + (tid - 64) * 4);
        else if (tid == 72) sdt[0] = g_dt[dtbase];
        else if (tid == 73) sdA[0] = g_dA[dtbase];
    }

    for (int t = 0; t < LL; t++) {
        __syncthreads();
        const int cur = t & 1;
        if (t + 1 < LL) {
            const float* rb = base + (size_t)(t + 1) * CONVDIM;
            const int nxt = cur ^ 1;
            if (tid < 32)       sB[nxt][tid]      = *(const float4*)(rb + DSSM + tid * 4);
            else if (tid < 64)  sC[nxt][tid - 32] = *(const float4*)(rb + DSSM + DSTATE + (tid - 32) * 4);
            else if (tid < 72)  sx[nxt][tid - 64] = *(const float4*)(rb + h * HD + p_base + (tid - 64) * 4);
            else if (tid == 72) sdt[nxt] = g_dt[dtbase + (size_t)(t + 1) * NH];
            else if (tid == 73) sdA[nxt] = g_dA[dtbase + (size_t)(t + 1) * NH];
        }

        const float dtv = sdt[cur];
        const float dAv = sdA[cur];
        const float4 Bv = sB[cur][lane];
        const float4 Cv = sC[cur][lane];
        const float4 xv = sx[cur][w];

        const float bb[4] = {Bv.x, Bv.y, Bv.z, Bv.w};
        const float cc[4] = {Cv.x, Cv.y, Cv.z, Cv.w};
        const float xx[4] = {xv.x, xv.y, xv.z, xv.w};

        float acc[4] = {0.f, 0.f, 0.f, 0.f};
#pragma unroll
        for (int i = 0; i < 4; i++) {
            const float dtx = dtv * xx[i];
#pragma unroll
            for (int j = 0; j < 4; j++) {
                hs[i][j] = fmaf(hs[i][j], dAv, dtx * bb[j]);
                acc[i] = fmaf(hs[i][j], cc[j], acc[i]);
            }
        }
        // reduce each acc over all 32 lanes (n dimension)
#pragma unroll
        for (int i = 0; i < 4; i++) {
            float a = acc[i];
            a += __shfl_xor_sync(0xffffffffu, a, 16);
            a += __shfl_xor_sync(0xffffffffu, a, 8);
            a += __shfl_xor_sync(0xffffffffu, a, 4);
            a += __shfl_xor_sync(0xffffffffu, a, 2);
            a += __shfl_xor_sync(0xffffffffu, a, 1);
            acc[i] = a;
        }
        if (lane < 4) {
            float res = (lane == 0) ? acc[0] : (lane == 1) ? acc[1] : (lane == 2) ? acc[2] : acc[3];
            float xval = (lane == 0) ? xv.x : (lane == 1) ? xv.y : (lane == 2) ? xv.z : xv.w;
            yout[(size_t)t * DSSM + p0 + lane] = fmaf(Dh, xval, res);
        }
    }
}

// ---------------- gate (silu(z)) + RMSNorm (in place on g_y) ----------------
__global__ __launch_bounds__(256) void gate_rmsnorm_kernel(const float* __restrict__ norm_w)
{
    const int row = blockIdx.x;      // 0..8191
    const int tid = threadIdx.x;
    const int w = tid >> 5, lane = tid & 31;

    float vals[8];
    float ss = 0.f;
#pragma unroll
    for (int i = 0; i < 8; i++) {
        int e = i * 256 + tid;
        float z = g_zxbcdt[(size_t)row * DPROJ + e];
        float yv = g_y[(size_t)row * DSSM + e];
        float g = yv * silu_f(z);
        vals[i] = g;
        ss = fmaf(g, g, ss);
    }
    ss += __shfl_xor_sync(0xffffffffu, ss, 16);
    ss += __shfl_xor_sync(0xffffffffu, ss, 8);
    ss += __shfl_xor_sync(0xffffffffu, ss, 4);
    ss += __shfl_xor_sync(0xffffffffu, ss, 2);
    ss += __shfl_xor_sync(0xffffffffu, ss, 1);

    __shared__ float red[8];
    __shared__ float sscale;
    if (lane == 0) red[w] = ss;
    __syncthreads();
    if (tid == 0) {
        float s = 0.f;
#pragma unroll
        for (int k = 0; k < 8; k++) s += red[k];
        sscale = rsqrtf(s / (float)DSSM + EPSV);
    }
    __syncthreads();
    const float scale = sscale;
#pragma unroll
    for (int i = 0; i < 8; i++) {
        int e = i * 256 + tid;
        g_y[(size_t)row * DSSM + e] = vals[i] * scale * norm_w[e];
    }
}

// ---------------- entry ----------------
extern "C" void kernel_launch(void* const* d_in, const int* in_sizes, int n_in,
                              void* d_out, int out_size)
{
    const float* u       = (const float*)d_in[0];  // [2,4096,1024]
    const float* W_in    = (const float*)d_in[1];  // [4384,1024]
    const float* conv_w  = (const float*)d_in[2];  // [2304,4]
    const float* conv_b  = (const float*)d_in[3];  // [2304]
    const float* dt_bias = (const float*)d_in[4];  // [32]
    const float* A_log   = (const float*)d_in[5];  // [32]
    const float* Dp      = (const float*)d_in[6];  // [32]
    const float* norm_w  = (const float*)d_in[7];  // [2048]
    const float* W_out   = (const float*)d_in[8];  // [1024,2048]
    float* out = (float*)d_out;                    // [2,4096,1024]

    float* zx;  cudaGetSymbolAddress((void**)&zx,  g_zxbcdt);
    float* gy;  cudaGetSymbolAddress((void**)&gy,  g_y);

    // 1) in-projection: zxbcdt = u @ W_in^T   (tf32 tensor cores + ldmatrix)
    {
        dim3 grid((DPROJ + 127) / 128, ROWS / 128);
        tf32gemm_nt_kernel<<<grid, 256>>>(u, W_in, zx, ROWS, DPROJ, DMODEL);
    }
    // 2) conv + silu
    {
        size_t total = (size_t)ROWS * CONVDIM;
        conv_silu_kernel<<<(unsigned)((total + 255) / 256), 256>>>(conv_w, conv_b);
    }
    // 3) dt softplus + dA
    dt_kernel<<<(ROWS * NH + 255) / 256, 256>>>(dt_bias, A_log);
    // 4) selective scan
    scan_kernel<<<128, 256>>>(Dp);
    // 5) gate + rmsnorm (in place on g_y)
    gate_rmsnorm_kernel<<<ROWS, 256>>>(norm_w);
    // 6) out-projection: out = g @ W_out^T   (tf32 tensor cores + ldmatrix)
    {
        dim3 grid(DMODEL / 128, ROWS / 128);
        tf32gemm_nt_kernel<<<grid, 256>>>(gy, W_out, out, ROWS, DMODEL, DSSM);
    }
}

// round 8
// speedup vs baseline: 1.5543x; 1.1048x over previous
#include <cuda_runtime.h>
#include <cuda_fp16.h>
#include <math.h>
#include <stdint.h>

// ---------------- Problem constants ----------------
#define BB      2
#define LL      4096
#define DMODEL  1024
#define DSSM    2048
#define DSTATE  128
#define DCONV   4
#define NH      32
#define HD      64
#define CONVDIM (DSSM + 2*DSTATE)          // 2304
#define DPROJ   (2*DSSM + 2*DSTATE + NH)   // 4384
#define EPSV    1e-5f

#define ROWS    (BB*LL)                    // 8192

// ---------------- Scratch (static device arrays; no allocation) ----------------
__device__ float  g_zxbcdt[(size_t)ROWS * DPROJ];   // in-proj output (fp32)
__device__ float  g_xbc[(size_t)ROWS * CONVDIM];    // conv+silu output
__device__ float  g_dt[(size_t)ROWS * NH];          // softplus(dt)
__device__ float  g_dA[(size_t)ROWS * NH];          // exp(dt*A)
__device__ float  g_y[(size_t)ROWS * DSSM];         // scan output (fp32)
__device__ __half g_uh[(size_t)ROWS * DMODEL];      // u in fp16
__device__ __half g_Winh[(size_t)DPROJ * DMODEL];   // W_in in fp16
__device__ __half g_gh[(size_t)ROWS * DSSM];        // normed gate output in fp16
__device__ __half g_Wouth[(size_t)DMODEL * DSSM];   // W_out in fp16

// ---------------- helpers ----------------
__device__ __forceinline__ float silu_f(float x) {
    return x / (1.0f + expf(-x));
}

__device__ __forceinline__ uint32_t smem_u32(const void* p) {
    uint32_t a;
    asm("{ .reg .u64 t; cvta.to.shared.u64 t, %1; cvt.u32.u64 %0, t; }" : "=r"(a) : "l"(p));
    return a;
}

__device__ __forceinline__ void ldsm4(uint32_t &r0, uint32_t &r1, uint32_t &r2, uint32_t &r3,
                                      uint32_t saddr) {
    asm volatile("ldmatrix.sync.aligned.m8n8.x4.shared.b16 {%0,%1,%2,%3}, [%4];"
                 : "=r"(r0), "=r"(r1), "=r"(r2), "=r"(r3)
                 : "r"(saddr));
}

__device__ __forceinline__ void cp_async16(uint32_t dst, const void* src, int srcsize) {
    asm volatile("cp.async.cg.shared.global [%0], [%1], 16, %2;"
                 :: "r"(dst), "l"(src), "r"(srcsize) : "memory");
}

// ---------------- fp16 tensor-core GEMM: C[m,n] = sum_k A[m,k]*B[n,k] (NT) ----------------
// BM=BN=128, BK=32 (fp16), 256 threads (8 warps), warp tile 32x64 via m16n8k16.
// cp.async double-buffered staging; ldmatrix.x4 fragment loads (conflict-free, 80B row stride).
// M % 128 == 0, K % 32 == 0; N ragged ok.
__global__ __launch_bounds__(256) void hgemm_nt_kernel(
    const __half* __restrict__ A, const __half* __restrict__ B, float* __restrict__ C,
    int M, int N, int K)
{
    __shared__ __align__(16) __half As[2][128][40];   // 40-half rows -> 80B stride
    __shared__ __align__(16) __half Bs[2][128][40];

    const int tid  = threadIdx.x;
    const int warp = tid >> 5;
    const int lane = tid & 31;
    const int g    = lane >> 2;     // epilogue row
    const int t4   = lane & 3;      // epilogue col pair
    const int wm   = (warp >> 1) * 32;
    const int wn   = (warp & 1) * 64;
    const int m0   = blockIdx.y * 128;
    const int n0   = blockIdx.x * 128;

    // ldmatrix lane -> address decomposition (same byte pattern as verified tf32 version)
    const int lm  = lane >> 3;
    const int lr  = lane & 7;
    const int arow = (lm & 1) * 8 + lr;   // A: m0-7 / m8-15
    const int acol = (lm >> 1) * 8;       // A: k0-7 / k8-15 (halves)
    const int brow = (lm >> 1) * 8 + lr;  // B: n0-7 / n8-15
    const int bcol = (lm & 1) * 8;        // B: k0-7 / k8-15 (halves)

    const uint32_t as_b = smem_u32(&As[0][0][0]);
    const uint32_t bs_b = smem_u32(&Bs[0][0][0]);
    const uint32_t BUFB = 128u * 40u * 2u;   // 10240 bytes per buffer

    float d[2][8][4];
#pragma unroll
    for (int i = 0; i < 2; i++)
#pragma unroll
        for (int j = 0; j < 8; j++)
#pragma unroll
            for (int v = 0; v < 4; v++) d[i][j][v] = 0.0f;

    const int nch = K >> 5;

    // stage(kc, buf): 512 16B segments per matrix, 2 per thread
    auto stage = [&](int kc, int buf) {
        const int kb = kc << 5;
#pragma unroll
        for (int i = 0; i < 2; i++) {
            const int f   = tid + (i << 8);
            const int row = f >> 2;
            const int seg = f & 3;
            const uint32_t off = (uint32_t)(row * 80 + seg * 16);
            cp_async16(as_b + (uint32_t)buf * BUFB + off,
                       &A[(size_t)(m0 + row) * K + kb + seg * 8], 16);
            const int nr = n0 + row;
            const int ok = (nr < N);
            cp_async16(bs_b + (uint32_t)buf * BUFB + off,
                       &B[(size_t)(ok ? nr : 0) * K + kb + seg * 8], ok ? 16 : 0);
        }
        asm volatile("cp.async.commit_group;" ::: "memory");
    };

    stage(0, 0);

    for (int kc = 0; kc < nch; kc++) {
        const int buf = kc & 1;
        if (kc + 1 < nch) {
            stage(kc + 1, buf ^ 1);
            asm volatile("cp.async.wait_group 1;" ::: "memory");
        } else {
            asm volatile("cp.async.wait_group 0;" ::: "memory");
        }
        __syncthreads();

        const uint32_t ab = as_b + (uint32_t)buf * BUFB;
        const uint32_t bb = bs_b + (uint32_t)buf * BUFB;
#pragma unroll
        for (int s = 0; s < 2; s++) {
            const int kk = s * 16;
            uint32_t af[2][4];
#pragma unroll
            for (int mt = 0; mt < 2; mt++) {
                uint32_t addr = ab + (uint32_t)(((wm + mt * 16 + arow) * 40 + kk + acol) * 2);
                ldsm4(af[mt][0], af[mt][1], af[mt][2], af[mt][3], addr);
            }
            uint32_t bf[8][2];
#pragma unroll
            for (int ntp = 0; ntp < 4; ntp++) {
                uint32_t q0, q1, q2, q3;
                uint32_t addr = bb + (uint32_t)(((wn + ntp * 16 + brow) * 40 + kk + bcol) * 2);
                ldsm4(q0, q1, q2, q3, addr);
                bf[2 * ntp][0]     = q0;  bf[2 * ntp][1]     = q1;
                bf[2 * ntp + 1][0] = q2;  bf[2 * ntp + 1][1] = q3;
            }
#pragma unroll
            for (int mt = 0; mt < 2; mt++) {
#pragma unroll
                for (int nt = 0; nt < 8; nt++) {
                    asm volatile(
                        "mma.sync.aligned.m16n8k16.row.col.f32.f16.f16.f32 "
                        "{%0,%1,%2,%3}, {%4,%5,%6,%7}, {%8,%9}, {%0,%1,%2,%3};"
                        : "+f"(d[mt][nt][0]), "+f"(d[mt][nt][1]),
                          "+f"(d[mt][nt][2]), "+f"(d[mt][nt][3])
                        : "r"(af[mt][0]), "r"(af[mt][1]), "r"(af[mt][2]), "r"(af[mt][3]),
                          "r"(bf[nt][0]), "r"(bf[nt][1]));
                }
            }
        }
        __syncthreads();
    }

    // epilogue: c0/c1 -> (row g, cols t4*2,+1); c2/c3 -> row g+8
#pragma unroll
    for (int mt = 0; mt < 2; mt++) {
        const int mrow = m0 + wm + mt * 16;
#pragma unroll
        for (int nt = 0; nt < 8; nt++) {
            const int ncol = n0 + wn + nt * 8 + t4 * 2;
            if (ncol < N) {
                *(float2*)&C[(size_t)(mrow + g    ) * N + ncol] =
                    make_float2(d[mt][nt][0], d[mt][nt][1]);
                *(float2*)&C[(size_t)(mrow + g + 8) * N + ncol] =
                    make_float2(d[mt][nt][2], d[mt][nt][3]);
            }
        }
    }
}

// ---------------- fp32 -> fp16 conversion (vectorized) ----------------
__global__ __launch_bounds__(256) void f2h_kernel(const float* __restrict__ src,
                                                  __half* __restrict__ dst, size_t n)
{
    size_t i = ((size_t)blockIdx.x * blockDim.x + threadIdx.x) * 4;
    if (i >= n) return;
    float4 v = *(const float4*)&src[i];
    __half2* d2 = (__half2*)&dst[i];
    d2[0] = __floats2half2_rn(v.x, v.y);
    d2[1] = __floats2half2_rn(v.z, v.w);
}

// ---------------- conv1d (width 4, causal) + bias + SiLU ----------------
__global__ __launch_bounds__(256) void conv_silu_kernel(
    const float* __restrict__ conv_w, const float* __restrict__ conv_b)
{
    size_t idx = (size_t)blockIdx.x * blockDim.x + threadIdx.x;
    if (idx >= (size_t)ROWS * CONVDIM) return;
    int c = (int)(idx % CONVDIM);
    size_t bt = idx / CONVDIM;
    int t = (int)(bt % LL);
    size_t brow0 = (bt - t); // (b*L) base row

    float accv = conv_b[c];
#pragma unroll
    for (int w = 0; w < DCONV; w++) {
        int ts = t - (DCONV - 1) + w;
        if (ts >= 0) {
            accv = fmaf(g_zxbcdt[(brow0 + ts) * (size_t)DPROJ + DSSM + c],
                        conv_w[c * DCONV + w], accv);
        }
    }
    g_xbc[idx] = silu_f(accv);
}

// ---------------- dt softplus + dA precompute ----------------
__global__ __launch_bounds__(256) void dt_kernel(
    const float* __restrict__ dt_bias, const float* __restrict__ A_log)
{
    int idx = blockIdx.x * blockDim.x + threadIdx.x;
    if (idx >= ROWS * NH) return;
    int h = idx % NH;
    int r = idx / NH;
    float raw = g_zxbcdt[(size_t)r * DPROJ + DSSM + CONVDIM + h] + dt_bias[h];
    float dt = (raw > 20.0f) ? raw : log1pf(expf(raw));
    float Aneg = -expf(A_log[h]);
    g_dt[idx] = dt;
    g_dA[idx] = expf(dt * Aneg);
}

// ---------------- selective scan ----------------
// 128 CTAs: (b, h, p-half). 256 threads: warp w -> 4 p's, lane -> 4 n's. State 4x4 regs.
__global__ __launch_bounds__(256) void scan_kernel(const float* __restrict__ Dp)
{
    const int blk = blockIdx.x;        // 0..127
    const int b = blk >> 6;
    const int hh = blk & 63;
    const int h = hh >> 1;
    const int p_base = (hh & 1) * 32;

    const int tid = threadIdx.x;
    const int w = tid >> 5;
    const int lane = tid & 31;
    const int p0 = p_base + w * 4;

    __shared__ float4 sB[2][32];
    __shared__ float4 sC[2][32];
    __shared__ float4 sx[2][8];
    __shared__ float sdt[2], sdA[2];

    float hs[4][4];
#pragma unroll
    for (int i = 0; i < 4; i++)
#pragma unroll
        for (int j = 0; j < 4; j++) hs[i][j] = 0.0f;

    const float Dh = Dp[h];
    const float* base = g_xbc + (size_t)b * LL * CONVDIM;
    const size_t dtbase = (size_t)b * LL * NH + h;
    float* yout = g_y + (size_t)b * LL * DSSM + h * HD;

    // stage 0 preload
    {
        const float* rb = base;
        if (tid < 32)       sB[0][tid]      = *(const float4*)(rb + DSSM + tid * 4);
        else if (tid < 64)  sC[0][tid - 32] = *(const float4*)(rb + DSSM + DSTATE + (tid - 32) * 4);
        else if (tid < 72)  sx[0][tid - 64] = *(const float4*)(rb + h * HD + p_base + (tid - 64) * 4);
        else if (tid == 72) sdt[0] = g_dt[dtbase];
        else if (tid == 73) sdA[0] = g_dA[dtbase];
    }

    for (int t = 0; t < LL; t++) {
        __syncthreads();
        const int cur = t & 1;
        if (t + 1 < LL) {
            const float* rb = base + (size_t)(t + 1) * CONVDIM;
            const int nxt = cur ^ 1;
            if (tid < 32)       sB[nxt][tid]      = *(const float4*)(rb + DSSM + tid * 4);
            else if (tid < 64)  sC[nxt][tid - 32] = *(const float4*)(rb + DSSM + DSTATE + (tid - 32) * 4);
            else if (tid < 72)  sx[nxt][tid - 64] = *(const float4*)(rb + h * HD + p_base + (tid - 64) * 4);
            else if (tid == 72) sdt[nxt] = g_dt[dtbase + (size_t)(t + 1) * NH];
            else if (tid == 73) sdA[nxt] = g_dA[dtbase + (size_t)(t + 1) * NH];
        }

        const float dtv = sdt[cur];
        const float dAv = sdA[cur];
        const float4 Bv = sB[cur][lane];
        const float4 Cv = sC[cur][lane];
        const float4 xv = sx[cur][w];

        const float bb[4] = {Bv.x, Bv.y, Bv.z, Bv.w};
        const float cc[4] = {Cv.x, Cv.y, Cv.z, Cv.w};
        const float xx[4] = {xv.x, xv.y, xv.z, xv.w};

        float acc[4] = {0.f, 0.f, 0.f, 0.f};
#pragma unroll
        for (int i = 0; i < 4; i++) {
            const float dtx = dtv * xx[i];
#pragma unroll
            for (int j = 0; j < 4; j++) {
                hs[i][j] = fmaf(hs[i][j], dAv, dtx * bb[j]);
                acc[i] = fmaf(hs[i][j], cc[j], acc[i]);
            }
        }
        // reduce each acc over all 32 lanes (n dimension)
#pragma unroll
        for (int i = 0; i < 4; i++) {
            float a = acc[i];
            a += __shfl_xor_sync(0xffffffffu, a, 16);
            a += __shfl_xor_sync(0xffffffffu, a, 8);
            a += __shfl_xor_sync(0xffffffffu, a, 4);
            a += __shfl_xor_sync(0xffffffffu, a, 2);
            a += __shfl_xor_sync(0xffffffffu, a, 1);
            acc[i] = a;
        }
        if (lane < 4) {
            float res = (lane == 0) ? acc[0] : (lane == 1) ? acc[1] : (lane == 2) ? acc[2] : acc[3];
            float xval = (lane == 0) ? xv.x : (lane == 1) ? xv.y : (lane == 2) ? xv.z : xv.w;
            yout[(size_t)t * DSSM + p0 + lane] = fmaf(Dh, xval, res);
        }
    }
}

// ---------------- gate (silu(z)) + RMSNorm -> fp16 output for GEMM2 ----------------
__global__ __launch_bounds__(256) void gate_rmsnorm_kernel(const float* __restrict__ norm_w)
{
    const int row = blockIdx.x;      // 0..8191
    const int tid = threadIdx.x;
    const int w = tid >> 5, lane = tid & 31;

    float vals[8];
    float ss = 0.f;
#pragma unroll
    for (int i = 0; i < 8; i++) {
        int e = i * 256 + tid;
        float z = g_zxbcdt[(size_t)row * DPROJ + e];
        float yv = g_y[(size_t)row * DSSM + e];
        float g = yv * silu_f(z);
        vals[i] = g;
        ss = fmaf(g, g, ss);
    }
    ss += __shfl_xor_sync(0xffffffffu, ss, 16);
    ss += __shfl_xor_sync(0xffffffffu, ss, 8);
    ss += __shfl_xor_sync(0xffffffffu, ss, 4);
    ss += __shfl_xor_sync(0xffffffffu, ss, 2);
    ss += __shfl_xor_sync(0xffffffffu, ss, 1);

    __shared__ float red[8];
    __shared__ float sscale;
    if (lane == 0) red[w] = ss;
    __syncthreads();
    if (tid == 0) {
        float s = 0.f;
#pragma unroll
        for (int k = 0; k < 8; k++) s += red[k];
        sscale = rsqrtf(s / (float)DSSM + EPSV);
    }
    __syncthreads();
    const float scale = sscale;
#pragma unroll
    for (int i = 0; i < 8; i++) {
        int e = i * 256 + tid;
        g_gh[(size_t)row * DSSM + e] = __float2half(vals[i] * scale * norm_w[e]);
    }
}

// ---------------- entry ----------------
extern "C" void kernel_launch(void* const* d_in, const int* in_sizes, int n_in,
                              void* d_out, int out_size)
{
    const float* u       = (const float*)d_in[0];  // [2,4096,1024]
    const float* W_in    = (const float*)d_in[1];  // [4384,1024]
    const float* conv_w  = (const float*)d_in[2];  // [2304,4]
    const float* conv_b  = (const float*)d_in[3];  // [2304]
    const float* dt_bias = (const float*)d_in[4];  // [32]
    const float* A_log   = (const float*)d_in[5];  // [32]
    const float* Dp      = (const float*)d_in[6];  // [32]
    const float* norm_w  = (const float*)d_in[7];  // [2048]
    const float* W_out   = (const float*)d_in[8];  // [1024,2048]
    float* out = (float*)d_out;                    // [2,4096,1024]

    float*  zx;  cudaGetSymbolAddress((void**)&zx,  g_zxbcdt);
    __half* uh;  cudaGetSymbolAddress((void**)&uh,  g_uh);
    __half* wih; cudaGetSymbolAddress((void**)&wih, g_Winh);
    __half* gh;  cudaGetSymbolAddress((void**)&gh,  g_gh);
    __half* woh; cudaGetSymbolAddress((void**)&woh, g_Wouth);

    // 0) fp32 -> fp16 conversions for GEMM inputs
    {
        size_t nu = (size_t)ROWS * DMODEL;
        f2h_kernel<<<(unsigned)((nu / 4 + 255) / 256), 256>>>(u, uh, nu);
        size_t nw = (size_t)DPROJ * DMODEL;
        f2h_kernel<<<(unsigned)((nw / 4 + 255) / 256), 256>>>(W_in, wih, nw);
        size_t no = (size_t)DMODEL * DSSM;
        f2h_kernel<<<(unsigned)((no / 4 + 255) / 256), 256>>>(W_out, woh, no);
    }
    // 1) in-projection: zxbcdt = u @ W_in^T   (fp16 tensor cores, cp.async pipeline)
    {
        dim3 grid((DPROJ + 127) / 128, ROWS / 128);
        hgemm_nt_kernel<<<grid, 256>>>(uh, wih, zx, ROWS, DPROJ, DMODEL);
    }
    // 2) conv + silu
    {
        size_t total = (size_t)ROWS * CONVDIM;
        conv_silu_kernel<<<(unsigned)((total + 255) / 256), 256>>>(conv_w, conv_b);
    }
    // 3) dt softplus + dA
    dt_kernel<<<(ROWS * NH + 255) / 256, 256>>>(dt_bias, A_log);
    // 4) selective scan
    scan_kernel<<<128, 256>>>(Dp);
    // 5) gate + rmsnorm (writes fp16 g_gh)
    gate_rmsnorm_kernel<<<ROWS, 256>>>(norm_w);
    // 6) out-projection: out = g @ W_out^T   (fp16 tensor cores)
    {
        dim3 grid(DMODEL / 128, ROWS / 128);
        hgemm_nt_kernel<<<grid, 256>>>(gh, woh, out, ROWS, DMODEL, DSSM);
    }
}

// round 9
// speedup vs baseline: 6.7842x; 4.3647x over previous
#include <cuda_runtime.h>
#include <cuda_fp16.h>
#include <math.h>
#include <stdint.h>

// ---------------- Problem constants ----------------
#define BB      2
#define LL      4096
#define DMODEL  1024
#define DSSM    2048
#define DSTATE  128
#define DCONV   4
#define NH      32
#define HD      64
#define CONVDIM (DSSM + 2*DSTATE)          // 2304
#define DPROJ   (2*DSSM + 2*DSTATE + NH)   // 4384
#define EPSV    1e-5f

#define ROWS    (BB*LL)                    // 8192
#define CT      64                         // chunk length
#define NCHUNK  (LL/CT)                    // 64
#define NSLOT   (BB*NH*NCHUNK)             // 4096

// ---------------- Scratch (static device arrays; no allocation) ----------------
__device__ float  g_zxbcdt[(size_t)ROWS * DPROJ];   // in-proj output (fp32)
__device__ float  g_xbc[(size_t)ROWS * CONVDIM];    // conv+silu output
__device__ float  g_dtT[(size_t)NH * ROWS];         // softplus(dt), transposed [h][row]
__device__ float  g_ldAT[(size_t)NH * ROWS];        // dt*A (log decay), transposed [h][row]
__device__ float  g_y[(size_t)ROWS * DSSM];         // scan output (fp32)
__device__ float  g_dH[(size_t)NSLOT * HD * DSTATE];   // chunk state increments (134MB)
__device__ float  g_hpre[(size_t)NSLOT * HD * DSTATE]; // chunk state prefixes (134MB)
__device__ float  g_cumlog[(size_t)NSLOT * CT];     // in-chunk cumulative log decay
__device__ float  g_clend[NSLOT];                   // chunk-end cumulative log decay
__device__ __half g_uh[(size_t)ROWS * DMODEL];      // u in fp16
__device__ __half g_Winh[(size_t)DPROJ * DMODEL];   // W_in in fp16
__device__ __half g_gh[(size_t)ROWS * DSSM];        // normed gate output in fp16
__device__ __half g_Wouth[(size_t)DMODEL * DSSM];   // W_out in fp16

// ---------------- helpers ----------------
__device__ __forceinline__ float silu_f(float x) {
    return x / (1.0f + expf(-x));
}

__device__ __forceinline__ uint32_t smem_u32(const void* p) {
    uint32_t a;
    asm("{ .reg .u64 t; cvta.to.shared.u64 t, %1; cvt.u32.u64 %0, t; }" : "=r"(a) : "l"(p));
    return a;
}

__device__ __forceinline__ void ldsm4(uint32_t &r0, uint32_t &r1, uint32_t &r2, uint32_t &r3,
                                      uint32_t saddr) {
    asm volatile("ldmatrix.sync.aligned.m8n8.x4.shared.b16 {%0,%1,%2,%3}, [%4];"
                 : "=r"(r0), "=r"(r1), "=r"(r2), "=r"(r3)
                 : "r"(saddr));
}

__device__ __forceinline__ void cp_async16(uint32_t dst, const void* src, int srcsize) {
    asm volatile("cp.async.cg.shared.global [%0], [%1], 16, %2;"
                 :: "r"(dst), "l"(src), "r"(srcsize) : "memory");
}

// ---------------- fp16 tensor-core GEMM: C[m,n] = sum_k A[m,k]*B[n,k] (NT) ----------------
__global__ __launch_bounds__(256) void hgemm_nt_kernel(
    const __half* __restrict__ A, const __half* __restrict__ B, float* __restrict__ C,
    int M, int N, int K)
{
    __shared__ __align__(16) __half As[2][128][40];
    __shared__ __align__(16) __half Bs[2][128][40];

    const int tid  = threadIdx.x;
    const int warp = tid >> 5;
    const int lane = tid & 31;
    const int g    = lane >> 2;
    const int t4   = lane & 3;
    const int wm   = (warp >> 1) * 32;
    const int wn   = (warp & 1) * 64;
    const int m0   = blockIdx.y * 128;
    const int n0   = blockIdx.x * 128;

    const int lm  = lane >> 3;
    const int lr  = lane & 7;
    const int arow = (lm & 1) * 8 + lr;
    const int acol = (lm >> 1) * 8;
    const int brow = (lm >> 1) * 8 + lr;
    const int bcol = (lm & 1) * 8;

    const uint32_t as_b = smem_u32(&As[0][0][0]);
    const uint32_t bs_b = smem_u32(&Bs[0][0][0]);
    const uint32_t BUFB = 128u * 40u * 2u;

    float d[2][8][4];
#pragma unroll
    for (int i = 0; i < 2; i++)
#pragma unroll
        for (int j = 0; j < 8; j++)
#pragma unroll
            for (int v = 0; v < 4; v++) d[i][j][v] = 0.0f;

    const int nch = K >> 5;

    auto stage = [&](int kc, int buf) {
        const int kb = kc << 5;
#pragma unroll
        for (int i = 0; i < 2; i++) {
            const int f   = tid + (i << 8);
            const int row = f >> 2;
            const int seg = f & 3;
            const uint32_t off = (uint32_t)(row * 80 + seg * 16);
            cp_async16(as_b + (uint32_t)buf * BUFB + off,
                       &A[(size_t)(m0 + row) * K + kb + seg * 8], 16);
            const int nr = n0 + row;
            const int ok = (nr < N);
            cp_async16(bs_b + (uint32_t)buf * BUFB + off,
                       &B[(size_t)(ok ? nr : 0) * K + kb + seg * 8], ok ? 16 : 0);
        }
        asm volatile("cp.async.commit_group;" ::: "memory");
    };

    stage(0, 0);

    for (int kc = 0; kc < nch; kc++) {
        const int buf = kc & 1;
        if (kc + 1 < nch) {
            stage(kc + 1, buf ^ 1);
            asm volatile("cp.async.wait_group 1;" ::: "memory");
        } else {
            asm volatile("cp.async.wait_group 0;" ::: "memory");
        }
        __syncthreads();

        const uint32_t ab = as_b + (uint32_t)buf * BUFB;
        const uint32_t bb = bs_b + (uint32_t)buf * BUFB;
#pragma unroll
        for (int s = 0; s < 2; s++) {
            const int kk = s * 16;
            uint32_t af[2][4];
#pragma unroll
            for (int mt = 0; mt < 2; mt++) {
                uint32_t addr = ab + (uint32_t)(((wm + mt * 16 + arow) * 40 + kk + acol) * 2);
                ldsm4(af[mt][0], af[mt][1], af[mt][2], af[mt][3], addr);
            }
            uint32_t bf[8][2];
#pragma unroll
            for (int ntp = 0; ntp < 4; ntp++) {
                uint32_t q0, q1, q2, q3;
                uint32_t addr = bb + (uint32_t)(((wn + ntp * 16 + brow) * 40 + kk + bcol) * 2);
                ldsm4(q0, q1, q2, q3, addr);
                bf[2 * ntp][0]     = q0;  bf[2 * ntp][1]     = q1;
                bf[2 * ntp + 1][0] = q2;  bf[2 * ntp + 1][1] = q3;
            }
#pragma unroll
            for (int mt = 0; mt < 2; mt++) {
#pragma unroll
                for (int nt = 0; nt < 8; nt++) {
                    asm volatile(
                        "mma.sync.aligned.m16n8k16.row.col.f32.f16.f16.f32 "
                        "{%0,%1,%2,%3}, {%4,%5,%6,%7}, {%8,%9}, {%0,%1,%2,%3};"
                        : "+f"(d[mt][nt][0]), "+f"(d[mt][nt][1]),
                          "+f"(d[mt][nt][2]), "+f"(d[mt][nt][3])
                        : "r"(af[mt][0]), "r"(af[mt][1]), "r"(af[mt][2]), "r"(af[mt][3]),
                          "r"(bf[nt][0]), "r"(bf[nt][1]));
                }
            }
        }
        __syncthreads();
    }

#pragma unroll
    for (int mt = 0; mt < 2; mt++) {
        const int mrow = m0 + wm + mt * 16;
#pragma unroll
        for (int nt = 0; nt < 8; nt++) {
            const int ncol = n0 + wn + nt * 8 + t4 * 2;
            if (ncol < N) {
                *(float2*)&C[(size_t)(mrow + g    ) * N + ncol] =
                    make_float2(d[mt][nt][0], d[mt][nt][1]);
                *(float2*)&C[(size_t)(mrow + g + 8) * N + ncol] =
                    make_float2(d[mt][nt][2], d[mt][nt][3]);
            }
        }
    }
}

// ---------------- fp32 -> fp16 conversion (vectorized) ----------------
__global__ __launch_bounds__(256) void f2h_kernel(const float* __restrict__ src,
                                                  __half* __restrict__ dst, size_t n)
{
    size_t i = ((size_t)blockIdx.x * blockDim.x + threadIdx.x) * 4;
    if (i >= n) return;
    float4 v = *(const float4*)&src[i];
    __half2* d2 = (__half2*)&dst[i];
    d2[0] = __floats2half2_rn(v.x, v.y);
    d2[1] = __floats2half2_rn(v.z, v.w);
}

// ---------------- conv1d (width 4, causal) + bias + SiLU ----------------
__global__ __launch_bounds__(256) void conv_silu_kernel(
    const float* __restrict__ conv_w, const float* __restrict__ conv_b)
{
    size_t idx = (size_t)blockIdx.x * blockDim.x + threadIdx.x;
    if (idx >= (size_t)ROWS * CONVDIM) return;
    int c = (int)(idx % CONVDIM);
    size_t bt = idx / CONVDIM;
    int t = (int)(bt % LL);
    size_t brow0 = (bt - t);

    float accv = conv_b[c];
#pragma unroll
    for (int w = 0; w < DCONV; w++) {
        int ts = t - (DCONV - 1) + w;
        if (ts >= 0) {
            accv = fmaf(g_zxbcdt[(brow0 + ts) * (size_t)DPROJ + DSSM + c],
                        conv_w[c * DCONV + w], accv);
        }
    }
    g_xbc[idx] = silu_f(accv);
}

// ---------------- dt softplus + log-decay (transposed layouts) ----------------
__global__ __launch_bounds__(256) void dt_kernel(
    const float* __restrict__ dt_bias, const float* __restrict__ A_log)
{
    int idx = blockIdx.x * blockDim.x + threadIdx.x;
    if (idx >= ROWS * NH) return;
    int h = idx % NH;
    int r = idx / NH;
    float raw = g_zxbcdt[(size_t)r * DPROJ + DSSM + CONVDIM + h] + dt_bias[h];
    float dt = (raw > 20.0f) ? raw : log1pf(expf(raw));
    float Aneg = -expf(A_log[h]);
    g_dtT[(size_t)h * ROWS + r] = dt;
    g_ldAT[(size_t)h * ROWS + r] = dt * Aneg;   // log(dA)
}

// ================= Chunked SSD scan =================
// slot s = ((b*NH + h)*NCHUNK + c); grid.x = NSLOT for phases A/C.

// ---------------- Phase A: per-chunk state increment ----------------
// dH[p][n] = sum_tau exp(cl[end]-cl[tau]) * dt*x[tau][p] * B[tau][n]
__global__ __launch_bounds__(256) void ssd_phaseA_kernel()
{
    extern __shared__ float sm[];
    float* s_B    = sm;                    // [64][132]
    float* s_wdtx = sm + 64 * 132;         // [64][68]  (tau-major, p fast)
    float* s_w    = s_wdtx + 64 * 68;      // [64]
    float* s_cl   = s_w + 64;              // [64]

    const int tid = threadIdx.x;
    const int bx  = blockIdx.x;
    const int c   = bx & (NCHUNK - 1);
    const int bh  = bx >> 6;
    const int b   = bh >> 5;
    const int h   = bh & 31;
    const int t0row = b * LL + c * CT;

    // cumulative log decay (thread 0, serial over 64)
    if (tid == 0) {
        float cl = 0.f;
        const float* ld = g_ldAT + (size_t)h * ROWS + t0row;
#pragma unroll 4
        for (int t = 0; t < CT; t++) { cl += ld[t]; s_cl[t] = cl; }
    }
    // load B tile [64][128] -> s_B padded 132
#pragma unroll
    for (int i = 0; i < 8; i++) {
        const int f = tid + (i << 8);       // 0..2047 float4s
        const int row = f >> 5;
        const int q = (f & 31) << 2;
        float4 v = *(const float4*)&g_xbc[(size_t)(t0row + row) * CONVDIM + DSSM + q];
        *(float4*)&s_B[row * 132 + q] = v;
    }
    __syncthreads();

    const float cend = s_cl[CT - 1];
    if (tid < CT) {
        s_w[tid] = expf(cend - s_cl[tid]);
        g_cumlog[(size_t)bx * CT + tid] = s_cl[tid];
        if (tid == 0) g_clend[bx] = cend;
    }
    __syncthreads();

    // build weighted dtx: s_wdtx[tau][p] = w[tau]*dt[tau]*x[tau][p]
#pragma unroll
    for (int i = 0; i < 16; i++) {
        const int f = tid + (i << 8);       // 0..4095
        const int tau = f & 63;
        const int p = f >> 6;
        const float dt = g_dtT[(size_t)h * ROWS + t0row + tau];
        const float xv = g_xbc[(size_t)(t0row + tau) * CONVDIM + h * HD + p];
        s_wdtx[tau * 68 + p] = s_w[tau] * dt * xv;
    }
    __syncthreads();

    // GEMM: dH[p][n] = sum_tau wdtx[tau][p] * B[tau][n]; thread tile 4p x 8n
    const int pp = tid >> 4;      // 0..15 -> p0 = 4*pp
    const int nu = tid & 15;      // n0 = 8*nu
    const int p0 = pp << 2;
    const int n0 = nu << 3;
    float acc[4][8];
#pragma unroll
    for (int i = 0; i < 4; i++)
#pragma unroll
        for (int j = 0; j < 8; j++) acc[i][j] = 0.f;

#pragma unroll 4
    for (int t4_ = 0; t4_ < 16; t4_++) {
        const int tau = t4_ << 2;
        float4 wv[4];
        float4 bv[4][2];
#pragma unroll
        for (int k = 0; k < 4; k++) {
            wv[k] = *(const float4*)&s_wdtx[(tau + k) * 68 + p0];
            bv[k][0] = *(const float4*)&s_B[(tau + k) * 132 + n0];
            bv[k][1] = *(const float4*)&s_B[(tau + k) * 132 + n0 + 4];
        }
#pragma unroll
        for (int k = 0; k < 4; k++) {
            const float w0 = wv[k].x, w1 = wv[k].y, w2 = wv[k].z, w3 = wv[k].w;
            const float* bp = (const float*)&bv[k][0];
#pragma unroll
            for (int j = 0; j < 8; j++) {
                acc[0][j] = fmaf(w0, bp[j], acc[0][j]);
                acc[1][j] = fmaf(w1, bp[j], acc[1][j]);
                acc[2][j] = fmaf(w2, bp[j], acc[2][j]);
                acc[3][j] = fmaf(w3, bp[j], acc[3][j]);
            }
        }
    }
    float* dh = g_dH + (size_t)bx * (HD * DSTATE);
#pragma unroll
    for (int i = 0; i < 4; i++) {
        *(float4*)&dh[(p0 + i) * DSTATE + n0]     =
            make_float4(acc[i][0], acc[i][1], acc[i][2], acc[i][3]);
        *(float4*)&dh[(p0 + i) * DSTATE + n0 + 4] =
            make_float4(acc[i][4], acc[i][5], acc[i][6], acc[i][7]);
    }
}

// ---------------- Phase B: chunk-level recurrence ----------------
// grid = BB*NH CTAs; each thread owns 32 state elements across 64 chunks.
__global__ __launch_bounds__(256) void ssd_phaseB_kernel()
{
    const int tid = threadIdx.x;
    const int bh  = blockIdx.x;           // 0..63
    float4 hreg[8];
#pragma unroll
    for (int j = 0; j < 8; j++) hreg[j] = make_float4(0.f, 0.f, 0.f, 0.f);

    for (int c = 0; c < NCHUNK; c++) {
        const size_t slot = (size_t)(bh * NCHUNK + c);
        const float* dh = g_dH + slot * (HD * DSTATE);
        float* hp = g_hpre + slot * (HD * DSTATE);
        const float P = expf(g_clend[slot]);
#pragma unroll
        for (int j = 0; j < 8; j++) {
            const int e = (tid + (j << 8)) << 2;
            float4 d4 = *(const float4*)&dh[e];
            *(float4*)&hp[e] = hreg[j];              // prefix (state BEFORE chunk c)
            hreg[j].x = fmaf(hreg[j].x, P, d4.x);
            hreg[j].y = fmaf(hreg[j].y, P, d4.y);
            hreg[j].z = fmaf(hreg[j].z, P, d4.z);
            hreg[j].w = fmaf(hreg[j].w, P, d4.w);
        }
    }
}

// ---------------- Phase C: per-chunk output ----------------
__global__ __launch_bounds__(256) void ssd_phaseC_kernel(const float* __restrict__ Dp)
{
    extern __shared__ float sm[];
    float* s_C   = sm;                       // [64][132]
    float* s_BT  = s_C + 64 * 132;           // [128][68]  (n-major, tau fast)
    float* s_hT  = s_BT + 128 * 68;          // [128][68]  (n-major, p fast)
    float* s_dtx = s_hT + 128 * 68;          // [64][68]   (tau-major, p fast)
    float* s_Gm  = s_dtx + 64 * 68;          // [64][68]   (t-major, tau fast)
    float* s_cl  = s_Gm + 64 * 68;           // [64]

    const int tid = threadIdx.x;
    const int bx  = blockIdx.x;
    const int c   = bx & (NCHUNK - 1);
    const int bh  = bx >> 6;
    const int b   = bh >> 5;
    const int h   = bh & 31;
    const int t0row = b * LL + c * CT;
    const float Dh = Dp[h];

    // loads
#pragma unroll
    for (int i = 0; i < 8; i++) {
        const int f = tid + (i << 8);        // 0..2047 float4s
        const int row = f >> 5;
        const int q = (f & 31) << 2;
        // C tile [64][128]
        float4 cv = *(const float4*)&g_xbc[(size_t)(t0row + row) * CONVDIM + DSSM + DSTATE + q];
        *(float4*)&s_C[row * 132 + q] = cv;
        // B tile -> transposed s_BT[n][tau]
        float4 bv = *(const float4*)&g_xbc[(size_t)(t0row + row) * CONVDIM + DSSM + q];
        s_BT[(q + 0) * 68 + row] = bv.x;
        s_BT[(q + 1) * 68 + row] = bv.y;
        s_BT[(q + 2) * 68 + row] = bv.z;
        s_BT[(q + 3) * 68 + row] = bv.w;
        // h_prefix [p][n] -> transposed s_hT[n][p]
        const int p = f >> 5;                // 0..63
        float4 hv = *(const float4*)&g_hpre[(size_t)bx * (HD * DSTATE) + p * DSTATE + q];
        s_hT[(q + 0) * 68 + p] = hv.x;
        s_hT[(q + 1) * 68 + p] = hv.y;
        s_hT[(q + 2) * 68 + p] = hv.z;
        s_hT[(q + 3) * 68 + p] = hv.w;
    }
#pragma unroll
    for (int i = 0; i < 16; i++) {
        const int f = tid + (i << 8);
        const int tau = f & 63;
        const int p = f >> 6;
        const float dt = g_dtT[(size_t)h * ROWS + t0row + tau];
        const float xv = g_xbc[(size_t)(t0row + tau) * CONVDIM + h * HD + p];
        s_dtx[tau * 68 + p] = dt * xv;
    }
    if (tid < CT) s_cl[tid] = g_cumlog[(size_t)bx * CT + tid];
    __syncthreads();

    const int tt = tid >> 4;       // 0..15
    const int tu = tid & 15;       // 0..15
    const int t0 = tt << 2;
    const int u0 = tu << 2;

    // G[t][u] = sum_n C[t][n]*B[u][n]
    {
        float acc[4][4];
#pragma unroll
        for (int i = 0; i < 4; i++)
#pragma unroll
            for (int j = 0; j < 4; j++) acc[i][j] = 0.f;
#pragma unroll 4
        for (int n4 = 0; n4 < 32; n4++) {
            const int n = n4 << 2;
            float4 cv[4], bv[4];
#pragma unroll
            for (int i = 0; i < 4; i++) cv[i] = *(const float4*)&s_C[(t0 + i) * 132 + n];
#pragma unroll
            for (int k = 0; k < 4; k++) bv[k] = *(const float4*)&s_BT[(n + k) * 68 + u0];
#pragma unroll
            for (int i = 0; i < 4; i++) {
#pragma unroll
                for (int j = 0; j < 4; j++) {
                    acc[i][j] = fmaf(cv[i].x, ((const float*)&bv[0])[j], acc[i][j]);
                    acc[i][j] = fmaf(cv[i].y, ((const float*)&bv[1])[j], acc[i][j]);
                    acc[i][j] = fmaf(cv[i].z, ((const float*)&bv[2])[j], acc[i][j]);
                    acc[i][j] = fmaf(cv[i].w, ((const float*)&bv[3])[j], acc[i][j]);
                }
            }
        }
        // mask + decay, write Gm
#pragma unroll
        for (int i = 0; i < 4; i++) {
            const int t = t0 + i;
            const float clt = s_cl[t];
#pragma unroll
            for (int j = 0; j < 4; j++) {
                const int u = u0 + j;
                s_Gm[t * 68 + u] = (u <= t) ? expf(clt - s_cl[u]) * acc[i][j] : 0.f;
            }
        }
    }
    __syncthreads();

    // Y[t][p] = sum_u Gm[t][u]*dtx[u][p]  +  exp(cl[t]) * sum_n C[t][n]*hT[n][p]  + D*x
    {
        const int p0 = tu << 2;
        float a1[4][4], a2[4][4];
#pragma unroll
        for (int i = 0; i < 4; i++)
#pragma unroll
            for (int j = 0; j < 4; j++) { a1[i][j] = 0.f; a2[i][j] = 0.f; }

#pragma unroll 4
        for (int u4 = 0; u4 < 16; u4++) {
            const int u = u4 << 2;
            float4 gv[4], dv[4];
#pragma unroll
            for (int i = 0; i < 4; i++) gv[i] = *(const float4*)&s_Gm[(t0 + i) * 68 + u];
#pragma unroll
            for (int k = 0; k < 4; k++) dv[k] = *(const float4*)&s_dtx[(u + k) * 68 + p0];
#pragma unroll
            for (int i = 0; i < 4; i++) {
#pragma unroll
                for (int j = 0; j < 4; j++) {
                    a1[i][j] = fmaf(gv[i].x, ((const float*)&dv[0])[j], a1[i][j]);
                    a1[i][j] = fmaf(gv[i].y, ((const float*)&dv[1])[j], a1[i][j]);
                    a1[i][j] = fmaf(gv[i].z, ((const float*)&dv[2])[j], a1[i][j]);
                    a1[i][j] = fmaf(gv[i].w, ((const float*)&dv[3])[j], a1[i][j]);
                }
            }
        }
#pragma unroll 4
        for (int n4 = 0; n4 < 32; n4++) {
            const int n = n4 << 2;
            float4 cv[4], hv[4];
#pragma unroll
            for (int i = 0; i < 4; i++) cv[i] = *(const float4*)&s_C[(t0 + i) * 132 + n];
#pragma unroll
            for (int k = 0; k < 4; k++) hv[k] = *(const float4*)&s_hT[(n + k) * 68 + p0];
#pragma unroll
            for (int i = 0; i < 4; i++) {
#pragma unroll
                for (int j = 0; j < 4; j++) {
                    a2[i][j] = fmaf(cv[i].x, ((const float*)&hv[0])[j], a2[i][j]);
                    a2[i][j] = fmaf(cv[i].y, ((const float*)&hv[1])[j], a2[i][j]);
                    a2[i][j] = fmaf(cv[i].z, ((const float*)&hv[2])[j], a2[i][j]);
                    a2[i][j] = fmaf(cv[i].w, ((const float*)&hv[3])[j], a2[i][j]);
                }
            }
        }
#pragma unroll
        for (int i = 0; i < 4; i++) {
            const int t = t0 + i;
            const int row = t0row + t;
            const float et = expf(s_cl[t]);
            float4 xv = *(const float4*)&g_xbc[(size_t)row * CONVDIM + h * HD + p0];
            float4 y4;
            y4.x = fmaf(et, a2[i][0], a1[i][0]) + Dh * xv.x;
            y4.y = fmaf(et, a2[i][1], a1[i][1]) + Dh * xv.y;
            y4.z = fmaf(et, a2[i][2], a1[i][2]) + Dh * xv.z;
            y4.w = fmaf(et, a2[i][3], a1[i][3]) + Dh * xv.w;
            *(float4*)&g_y[(size_t)row * DSSM + h * HD + p0] = y4;
        }
    }
}

// ---------------- gate (silu(z)) + RMSNorm -> fp16 output for GEMM2 ----------------
__global__ __launch_bounds__(256) void gate_rmsnorm_kernel(const float* __restrict__ norm_w)
{
    const int row = blockIdx.x;
    const int tid = threadIdx.x;
    const int w = tid >> 5, lane = tid & 31;

    float vals[8];
    float ss = 0.f;
#pragma unroll
    for (int i = 0; i < 8; i++) {
        int e = i * 256 + tid;
        float z = g_zxbcdt[(size_t)row * DPROJ + e];
        float yv = g_y[(size_t)row * DSSM + e];
        float g = yv * silu_f(z);
        vals[i] = g;
        ss = fmaf(g, g, ss);
    }
    ss += __shfl_xor_sync(0xffffffffu, ss, 16);
    ss += __shfl_xor_sync(0xffffffffu, ss, 8);
    ss += __shfl_xor_sync(0xffffffffu, ss, 4);
    ss += __shfl_xor_sync(0xffffffffu, ss, 2);
    ss += __shfl_xor_sync(0xffffffffu, ss, 1);

    __shared__ float red[8];
    __shared__ float sscale;
    if (lane == 0) red[w] = ss;
    __syncthreads();
    if (tid == 0) {
        float s = 0.f;
#pragma unroll
        for (int k = 0; k < 8; k++) s += red[k];
        sscale = rsqrtf(s / (float)DSSM + EPSV);
    }
    __syncthreads();
    const float scale = sscale;
#pragma unroll
    for (int i = 0; i < 8; i++) {
        int e = i * 256 + tid;
        g_gh[(size_t)row * DSSM + e] = __float2half(vals[i] * scale * norm_w[e]);
    }
}

// ---------------- entry ----------------
extern "C" void kernel_launch(void* const* d_in, const int* in_sizes, int n_in,
                              void* d_out, int out_size)
{
    const float* u       = (const float*)d_in[0];
    const float* W_in    = (const float*)d_in[1];
    const float* conv_w  = (const float*)d_in[2];
    const float* conv_b  = (const float*)d_in[3];
    const float* dt_bias = (const float*)d_in[4];
    const float* A_log   = (const float*)d_in[5];
    const float* Dp      = (const float*)d_in[6];
    const float* norm_w  = (const float*)d_in[7];
    const float* W_out   = (const float*)d_in[8];
    float* out = (float*)d_out;

    float*  zx;  cudaGetSymbolAddress((void**)&zx,  g_zxbcdt);
    __half* uh;  cudaGetSymbolAddress((void**)&uh,  g_uh);
    __half* wih; cudaGetSymbolAddress((void**)&wih, g_Winh);
    __half* gh;  cudaGetSymbolAddress((void**)&gh,  g_gh);
    __half* woh; cudaGetSymbolAddress((void**)&woh, g_Wouth);

    const int smA = (64 * 132 + 64 * 68 + 64 + 64) * 4;
    const int smC = (64 * 132 + 128 * 68 + 128 * 68 + 64 * 68 + 64 * 68 + 64) * 4;
    cudaFuncSetAttribute(ssd_phaseA_kernel, cudaFuncAttributeMaxDynamicSharedMemorySize, smA);
    cudaFuncSetAttribute(ssd_phaseC_kernel, cudaFuncAttributeMaxDynamicSharedMemorySize, smC);

    // 0) fp16 conversions
    {
        size_t nu = (size_t)ROWS * DMODEL;
        f2h_kernel<<<(unsigned)((nu / 4 + 255) / 256), 256>>>(u, uh, nu);
        size_t nw = (size_t)DPROJ * DMODEL;
        f2h_kernel<<<(unsigned)((nw / 4 + 255) / 256), 256>>>(W_in, wih, nw);
        size_t no = (size_t)DMODEL * DSSM;
        f2h_kernel<<<(unsigned)((no / 4 + 255) / 256), 256>>>(W_out, woh, no);
    }
    // 1) in-projection
    {
        dim3 grid((DPROJ + 127) / 128, ROWS / 128);
        hgemm_nt_kernel<<<grid, 256>>>(uh, wih, zx, ROWS, DPROJ, DMODEL);
    }
    // 2) conv + silu
    {
        size_t total = (size_t)ROWS * CONVDIM;
        conv_silu_kernel<<<(unsigned)((total + 255) / 256), 256>>>(conv_w, conv_b);
    }
    // 3) dt softplus + log decay
    dt_kernel<<<(ROWS * NH + 255) / 256, 256>>>(dt_bias, A_log);
    // 4) chunked SSD scan
    ssd_phaseA_kernel<<<NSLOT, 256, smA>>>();
    ssd_phaseB_kernel<<<BB * NH, 256>>>();
    ssd_phaseC_kernel<<<NSLOT, 256, smC>>>(Dp);
    // 5) gate + rmsnorm
    gate_rmsnorm_kernel<<<ROWS, 256>>>(norm_w);
    // 6) out-projection
    {
        dim3 grid(DMODEL / 128, ROWS / 128);
        hgemm_nt_kernel<<<grid, 256>>>(gh, woh, out, ROWS, DMODEL, DSSM);
    }
}

// round 10
// speedup vs baseline: 7.2170x; 1.0638x over previous
#include <cuda_runtime.h>
#include <cuda_fp16.h>
#include <math.h>
#include <stdint.h>

// ---------------- Problem constants ----------------
#define BB      2
#define LL      4096
#define DMODEL  1024
#define DSSM    2048
#define DSTATE  128
#define DCONV   4
#define NH      32
#define HD      64
#define CONVDIM (DSSM + 2*DSTATE)          // 2304
#define DPROJ   (2*DSSM + 2*DSTATE + NH)   // 4384
#define EPSV    1e-5f

#define ROWS    (BB*LL)                    // 8192
#define CT      64                         // chunk length
#define NCHUNK  (LL/CT)                    // 64
#define NSLOT   (BB*NH*NCHUNK)             // 4096

// ---------------- Scratch (static device arrays; no allocation) ----------------
__device__ float  g_zxbcdt[(size_t)ROWS * DPROJ];
__device__ float  g_xbc[(size_t)ROWS * CONVDIM];
__device__ float  g_dtT[(size_t)NH * ROWS];
__device__ float  g_ldAT[(size_t)NH * ROWS];
__device__ float  g_y[(size_t)ROWS * DSSM];
__device__ float  g_dH[(size_t)NSLOT * HD * DSTATE];
__device__ float  g_hpre[(size_t)NSLOT * HD * DSTATE];
__device__ float  g_cumlog[(size_t)NSLOT * CT];
__device__ float  g_clend[NSLOT];
__device__ __half g_uh[(size_t)ROWS * DMODEL];
__device__ __half g_Winh[(size_t)DPROJ * DMODEL];
__device__ __half g_gh[(size_t)ROWS * DSSM];
__device__ __half g_Wouth[(size_t)DMODEL * DSSM];

// ---------------- helpers ----------------
__device__ __forceinline__ float silu_f(float x) {
    return x / (1.0f + expf(-x));
}

__device__ __forceinline__ uint32_t smem_u32(const void* p) {
    uint32_t a;
    asm("{ .reg .u64 t; cvta.to.shared.u64 t, %1; cvt.u32.u64 %0, t; }" : "=r"(a) : "l"(p));
    return a;
}

__device__ __forceinline__ void ldsm4(uint32_t &r0, uint32_t &r1, uint32_t &r2, uint32_t &r3,
                                      uint32_t saddr) {
    asm volatile("ldmatrix.sync.aligned.m8n8.x4.shared.b16 {%0,%1,%2,%3}, [%4];"
                 : "=r"(r0), "=r"(r1), "=r"(r2), "=r"(r3)
                 : "r"(saddr));
}

__device__ __forceinline__ void cp_async16(uint32_t dst, const void* src, int srcsize) {
    asm volatile("cp.async.cg.shared.global [%0], [%1], 16, %2;"
                 :: "r"(dst), "l"(src), "r"(srcsize) : "memory");
}

// ---------------- fp16 tensor-core GEMM, 3-stage cp.async pipeline (NT) ----------------
// BM=BN=128, BK=32, 256 threads, warp tile 32x64 via m16n8k16. One sync per k-iter.
__global__ __launch_bounds__(256) void hgemm_nt_kernel(
    const __half* __restrict__ A, const __half* __restrict__ B, float* __restrict__ C,
    int M, int N, int K)
{
    __shared__ __align__(16) __half As[3][128][40];
    __shared__ __align__(16) __half Bs[3][128][40];

    const int tid  = threadIdx.x;
    const int warp = tid >> 5;
    const int lane = tid & 31;
    const int g    = lane >> 2;
    const int t4   = lane & 3;
    const int wm   = (warp >> 1) * 32;
    const int wn   = (warp & 1) * 64;
    const int m0   = blockIdx.y * 128;
    const int n0   = blockIdx.x * 128;

    const int lm  = lane >> 3;
    const int lr  = lane & 7;
    const int arow = (lm & 1) * 8 + lr;
    const int acol = (lm >> 1) * 8;
    const int brow = (lm >> 1) * 8 + lr;
    const int bcol = (lm & 1) * 8;

    const uint32_t as_b = smem_u32(&As[0][0][0]);
    const uint32_t bs_b = smem_u32(&Bs[0][0][0]);
    const uint32_t BUFB = 128u * 40u * 2u;   // 10240 bytes per buffer

    float d[2][8][4];
#pragma unroll
    for (int i = 0; i < 2; i++)
#pragma unroll
        for (int j = 0; j < 8; j++)
#pragma unroll
            for (int v = 0; v < 4; v++) d[i][j][v] = 0.0f;

    const int nch = K >> 5;

    auto stage = [&](int kc, int buf) {
        const int kb = kc << 5;
#pragma unroll
        for (int i = 0; i < 2; i++) {
            const int f   = tid + (i << 8);
            const int row = f >> 2;
            const int seg = f & 3;
            const uint32_t off = (uint32_t)(row * 80 + seg * 16);
            cp_async16(as_b + (uint32_t)buf * BUFB + off,
                       &A[(size_t)(m0 + row) * K + kb + seg * 8], 16);
            const int nr = n0 + row;
            const int ok = (nr < N);
            cp_async16(bs_b + (uint32_t)buf * BUFB + off,
                       &B[(size_t)(ok ? nr : 0) * K + kb + seg * 8], ok ? 16 : 0);
        }
        asm volatile("cp.async.commit_group;" ::: "memory");
    };

    stage(0, 0);
    if (nch > 1) stage(1, 1);

    for (int kc = 0; kc < nch; kc++) {
        const int buf = kc % 3;
        // wait for group kc to complete (allow 1 newer pending in steady state)
        if (kc + 1 < nch) {
            asm volatile("cp.async.wait_group 1;" ::: "memory");
        } else {
            asm volatile("cp.async.wait_group 0;" ::: "memory");
        }
        __syncthreads();   // buffer kc visible to all; buffer (kc+2)%3 free to overwrite
        if (kc + 2 < nch) stage(kc + 2, (kc + 2) % 3);

        const uint32_t ab = as_b + (uint32_t)buf * BUFB;
        const uint32_t bb = bs_b + (uint32_t)buf * BUFB;
#pragma unroll
        for (int s = 0; s < 2; s++) {
            const int kk = s * 16;
            uint32_t af[2][4];
#pragma unroll
            for (int mt = 0; mt < 2; mt++) {
                uint32_t addr = ab + (uint32_t)(((wm + mt * 16 + arow) * 40 + kk + acol) * 2);
                ldsm4(af[mt][0], af[mt][1], af[mt][2], af[mt][3], addr);
            }
            uint32_t bf[8][2];
#pragma unroll
            for (int ntp = 0; ntp < 4; ntp++) {
                uint32_t q0, q1, q2, q3;
                uint32_t addr = bb + (uint32_t)(((wn + ntp * 16 + brow) * 40 + kk + bcol) * 2);
                ldsm4(q0, q1, q2, q3, addr);
                bf[2 * ntp][0]     = q0;  bf[2 * ntp][1]     = q1;
                bf[2 * ntp + 1][0] = q2;  bf[2 * ntp + 1][1] = q3;
            }
#pragma unroll
            for (int mt = 0; mt < 2; mt++) {
#pragma unroll
                for (int nt = 0; nt < 8; nt++) {
                    asm volatile(
                        "mma.sync.aligned.m16n8k16.row.col.f32.f16.f16.f32 "
                        "{%0,%1,%2,%3}, {%4,%5,%6,%7}, {%8,%9}, {%0,%1,%2,%3};"
                        : "+f"(d[mt][nt][0]), "+f"(d[mt][nt][1]),
                          "+f"(d[mt][nt][2]), "+f"(d[mt][nt][3])
                        : "r"(af[mt][0]), "r"(af[mt][1]), "r"(af[mt][2]), "r"(af[mt][3]),
                          "r"(bf[nt][0]), "r"(bf[nt][1]));
                }
            }
        }
    }

#pragma unroll
    for (int mt = 0; mt < 2; mt++) {
        const int mrow = m0 + wm + mt * 16;
#pragma unroll
        for (int nt = 0; nt < 8; nt++) {
            const int ncol = n0 + wn + nt * 8 + t4 * 2;
            if (ncol < N) {
                *(float2*)&C[(size_t)(mrow + g    ) * N + ncol] =
                    make_float2(d[mt][nt][0], d[mt][nt][1]);
                *(float2*)&C[(size_t)(mrow + g + 8) * N + ncol] =
                    make_float2(d[mt][nt][2], d[mt][nt][3]);
            }
        }
    }
}

// ---------------- fp32 -> fp16 conversion (vectorized) ----------------
__global__ __launch_bounds__(256) void f2h_kernel(const float* __restrict__ src,
                                                  __half* __restrict__ dst, size_t n)
{
    size_t i = ((size_t)blockIdx.x * blockDim.x + threadIdx.x) * 4;
    if (i >= n) return;
    float4 v = *(const float4*)&src[i];
    __half2* d2 = (__half2*)&dst[i];
    d2[0] = __floats2half2_rn(v.x, v.y);
    d2[1] = __floats2half2_rn(v.z, v.w);
}

// ---------------- conv1d (width 4, causal) + bias + SiLU ----------------
__global__ __launch_bounds__(256) void conv_silu_kernel(
    const float* __restrict__ conv_w, const float* __restrict__ conv_b)
{
    size_t idx = (size_t)blockIdx.x * blockDim.x + threadIdx.x;
    if (idx >= (size_t)ROWS * CONVDIM) return;
    int c = (int)(idx % CONVDIM);
    size_t bt = idx / CONVDIM;
    int t = (int)(bt % LL);
    size_t brow0 = (bt - t);

    float accv = conv_b[c];
#pragma unroll
    for (int w = 0; w < DCONV; w++) {
        int ts = t - (DCONV - 1) + w;
        if (ts >= 0) {
            accv = fmaf(g_zxbcdt[(brow0 + ts) * (size_t)DPROJ + DSSM + c],
                        conv_w[c * DCONV + w], accv);
        }
    }
    g_xbc[idx] = silu_f(accv);
}

// ---------------- dt softplus + log-decay (transposed layouts) ----------------
__global__ __launch_bounds__(256) void dt_kernel(
    const float* __restrict__ dt_bias, const float* __restrict__ A_log)
{
    int idx = blockIdx.x * blockDim.x + threadIdx.x;
    if (idx >= ROWS * NH) return;
    int h = idx % NH;
    int r = idx / NH;
    float raw = g_zxbcdt[(size_t)r * DPROJ + DSSM + CONVDIM + h] + dt_bias[h];
    float dt = (raw > 20.0f) ? raw : log1pf(expf(raw));
    float Aneg = -expf(A_log[h]);
    g_dtT[(size_t)h * ROWS + r] = dt;
    g_ldAT[(size_t)h * ROWS + r] = dt * Aneg;
}

// ================= Chunked SSD scan =================

// ---------------- Phase A: per-chunk state increment ----------------
__global__ __launch_bounds__(256) void ssd_phaseA_kernel()
{
    extern __shared__ float sm[];
    float* s_B    = sm;                    // [64][132]
    float* s_wdtx = sm + 64 * 132;         // [64][68]
    float* s_w    = s_wdtx + 64 * 68;      // [64]
    float* s_cl   = s_w + 64;              // [64]

    const int tid = threadIdx.x;
    const int bx  = blockIdx.x;
    const int c   = bx & (NCHUNK - 1);
    const int bh  = bx >> 6;
    const int b   = bh >> 5;
    const int h   = bh & 31;
    const int t0row = b * LL + c * CT;

    if (tid == 0) {
        float cl = 0.f;
        const float* ld = g_ldAT + (size_t)h * ROWS + t0row;
#pragma unroll 4
        for (int t = 0; t < CT; t++) { cl += ld[t]; s_cl[t] = cl; }
    }
#pragma unroll
    for (int i = 0; i < 8; i++) {
        const int f = tid + (i << 8);
        const int row = f >> 5;
        const int q = (f & 31) << 2;
        float4 v = *(const float4*)&g_xbc[(size_t)(t0row + row) * CONVDIM + DSSM + q];
        *(float4*)&s_B[row * 132 + q] = v;
    }
    __syncthreads();

    const float cend = s_cl[CT - 1];
    if (tid < CT) {
        s_w[tid] = expf(cend - s_cl[tid]);
        g_cumlog[(size_t)bx * CT + tid] = s_cl[tid];
        if (tid == 0) g_clend[bx] = cend;
    }
    __syncthreads();

#pragma unroll
    for (int i = 0; i < 16; i++) {
        const int f = tid + (i << 8);
        const int tau = f & 63;
        const int p = f >> 6;
        const float dt = g_dtT[(size_t)h * ROWS + t0row + tau];
        const float xv = g_xbc[(size_t)(t0row + tau) * CONVDIM + h * HD + p];
        s_wdtx[tau * 68 + p] = s_w[tau] * dt * xv;
    }
    __syncthreads();

    const int pp = tid >> 4;
    const int nu = tid & 15;
    const int p0 = pp << 2;
    const int n0 = nu << 3;
    float acc[4][8];
#pragma unroll
    for (int i = 0; i < 4; i++)
#pragma unroll
        for (int j = 0; j < 8; j++) acc[i][j] = 0.f;

#pragma unroll 4
    for (int t4_ = 0; t4_ < 16; t4_++) {
        const int tau = t4_ << 2;
        float4 wv[4];
        float4 bv[4][2];
#pragma unroll
        for (int k = 0; k < 4; k++) {
            wv[k] = *(const float4*)&s_wdtx[(tau + k) * 68 + p0];
            bv[k][0] = *(const float4*)&s_B[(tau + k) * 132 + n0];
            bv[k][1] = *(const float4*)&s_B[(tau + k) * 132 + n0 + 4];
        }
#pragma unroll
        for (int k = 0; k < 4; k++) {
            const float w0 = wv[k].x, w1 = wv[k].y, w2 = wv[k].z, w3 = wv[k].w;
            const float* bp = (const float*)&bv[k][0];
#pragma unroll
            for (int j = 0; j < 8; j++) {
                acc[0][j] = fmaf(w0, bp[j], acc[0][j]);
                acc[1][j] = fmaf(w1, bp[j], acc[1][j]);
                acc[2][j] = fmaf(w2, bp[j], acc[2][j]);
                acc[3][j] = fmaf(w3, bp[j], acc[3][j]);
            }
        }
    }
    float* dh = g_dH + (size_t)bx * (HD * DSTATE);
#pragma unroll
    for (int i = 0; i < 4; i++) {
        *(float4*)&dh[(p0 + i) * DSTATE + n0]     =
            make_float4(acc[i][0], acc[i][1], acc[i][2], acc[i][3]);
        *(float4*)&dh[(p0 + i) * DSTATE + n0 + 4] =
            make_float4(acc[i][4], acc[i][5], acc[i][6], acc[i][7]);
    }
}

// ---------------- Phase B: chunk-level recurrence (fully parallel over state) ----------------
// grid = 512 CTAs x 256 threads; each thread owns ONE float4 of (bh, state) and
// loops over the 64 chunks. Coalesced 512B/warp; memory-bound.
__global__ __launch_bounds__(256) void ssd_phaseB_kernel()
{
    const int gid = blockIdx.x * 256 + threadIdx.x;    // 0..131071
    const int bh  = gid >> 11;                          // 2048 float4 per (b,h)
    const int e   = (gid & 2047) << 2;                  // float offset in state

    float4 h = make_float4(0.f, 0.f, 0.f, 0.f);
    const size_t sbase = (size_t)bh * NCHUNK;
    for (int c = 0; c < NCHUNK; c++) {
        const size_t slot = sbase + c;
        const float4 d4 = *(const float4*)&g_dH[slot * (HD * DSTATE) + e];
        *(float4*)&g_hpre[slot * (HD * DSTATE) + e] = h;
        const float P = expf(g_clend[slot]);
        h.x = fmaf(h.x, P, d4.x);
        h.y = fmaf(h.y, P, d4.y);
        h.z = fmaf(h.z, P, d4.z);
        h.w = fmaf(h.w, P, d4.w);
    }
}

// ---------------- Phase C: per-chunk output ----------------
__global__ __launch_bounds__(256) void ssd_phaseC_kernel(const float* __restrict__ Dp)
{
    extern __shared__ float sm[];
    float* s_C   = sm;                       // [64][132]
    float* s_BT  = s_C + 64 * 132;           // [128][68]
    float* s_hT  = s_BT + 128 * 68;          // [128][68]
    float* s_dtx = s_hT + 128 * 68;          // [64][68]
    float* s_Gm  = s_dtx + 64 * 68;          // [64][68]
    float* s_cl  = s_Gm + 64 * 68;           // [64]

    const int tid = threadIdx.x;
    const int bx  = blockIdx.x;
    const int c   = bx & (NCHUNK - 1);
    const int bh  = bx >> 6;
    const int b   = bh >> 5;
    const int h   = bh & 31;
    const int t0row = b * LL + c * CT;
    const float Dh = Dp[h];

#pragma unroll
    for (int i = 0; i < 8; i++) {
        const int f = tid + (i << 8);
        const int row = f >> 5;
        const int q = (f & 31) << 2;
        float4 cv = *(const float4*)&g_xbc[(size_t)(t0row + row) * CONVDIM + DSSM + DSTATE + q];
        *(float4*)&s_C[row * 132 + q] = cv;
        float4 bv = *(const float4*)&g_xbc[(size_t)(t0row + row) * CONVDIM + DSSM + q];
        s_BT[(q + 0) * 68 + row] = bv.x;
        s_BT[(q + 1) * 68 + row] = bv.y;
        s_BT[(q + 2) * 68 + row] = bv.z;
        s_BT[(q + 3) * 68 + row] = bv.w;
        const int p = f >> 5;
        float4 hv = *(const float4*)&g_hpre[(size_t)bx * (HD * DSTATE) + p * DSTATE + q];
        s_hT[(q + 0) * 68 + p] = hv.x;
        s_hT[(q + 1) * 68 + p] = hv.y;
        s_hT[(q + 2) * 68 + p] = hv.z;
        s_hT[(q + 3) * 68 + p] = hv.w;
    }
#pragma unroll
    for (int i = 0; i < 16; i++) {
        const int f = tid + (i << 8);
        const int tau = f & 63;
        const int p = f >> 6;
        const float dt = g_dtT[(size_t)h * ROWS + t0row + tau];
        const float xv = g_xbc[(size_t)(t0row + tau) * CONVDIM + h * HD + p];
        s_dtx[tau * 68 + p] = dt * xv;
    }
    if (tid < CT) s_cl[tid] = g_cumlog[(size_t)bx * CT + tid];
    __syncthreads();

    const int tt = tid >> 4;
    const int tu = tid & 15;
    const int t0 = tt << 2;
    const int u0 = tu << 2;

    {
        float acc[4][4];
#pragma unroll
        for (int i = 0; i < 4; i++)
#pragma unroll
            for (int j = 0; j < 4; j++) acc[i][j] = 0.f;
#pragma unroll 4
        for (int n4 = 0; n4 < 32; n4++) {
            const int n = n4 << 2;
            float4 cv[4], bv[4];
#pragma unroll
            for (int i = 0; i < 4; i++) cv[i] = *(const float4*)&s_C[(t0 + i) * 132 + n];
#pragma unroll
            for (int k = 0; k < 4; k++) bv[k] = *(const float4*)&s_BT[(n + k) * 68 + u0];
#pragma unroll
            for (int i = 0; i < 4; i++) {
#pragma unroll
                for (int j = 0; j < 4; j++) {
                    acc[i][j] = fmaf(cv[i].x, ((const float*)&bv[0])[j], acc[i][j]);
                    acc[i][j] = fmaf(cv[i].y, ((const float*)&bv[1])[j], acc[i][j]);
                    acc[i][j] = fmaf(cv[i].z, ((const float*)&bv[2])[j], acc[i][j]);
                    acc[i][j] = fmaf(cv[i].w, ((const float*)&bv[3])[j], acc[i][j]);
                }
            }
        }
#pragma unroll
        for (int i = 0; i < 4; i++) {
            const int t = t0 + i;
            const float clt = s_cl[t];
#pragma unroll
            for (int j = 0; j < 4; j++) {
                const int u = u0 + j;
                s_Gm[t * 68 + u] = (u <= t) ? expf(clt - s_cl[u]) * acc[i][j] : 0.f;
            }
        }
    }
    __syncthreads();

    {
        const int p0 = tu << 2;
        float a1[4][4], a2[4][4];
#pragma unroll
        for (int i = 0; i < 4; i++)
#pragma unroll
            for (int j = 0; j < 4; j++) { a1[i][j] = 0.f; a2[i][j] = 0.f; }

#pragma unroll 4
        for (int u4 = 0; u4 < 16; u4++) {
            const int u = u4 << 2;
            float4 gv[4], dv[4];
#pragma unroll
            for (int i = 0; i < 4; i++) gv[i] = *(const float4*)&s_Gm[(t0 + i) * 68 + u];
#pragma unroll
            for (int k = 0; k < 4; k++) dv[k] = *(const float4*)&s_dtx[(u + k) * 68 + p0];
#pragma unroll
            for (int i = 0; i < 4; i++) {
#pragma unroll
                for (int j = 0; j < 4; j++) {
                    a1[i][j] = fmaf(gv[i].x, ((const float*)&dv[0])[j], a1[i][j]);
                    a1[i][j] = fmaf(gv[i].y, ((const float*)&dv[1])[j], a1[i][j]);
                    a1[i][j] = fmaf(gv[i].z, ((const float*)&dv[2])[j], a1[i][j]);
                    a1[i][j] = fmaf(gv[i].w, ((const float*)&dv[3])[j], a1[i][j]);
                }
            }
        }
#pragma unroll 4
        for (int n4 = 0; n4 < 32; n4++) {
            const int n = n4 << 2;
            float4 cv[4], hv[4];
#pragma unroll
            for (int i = 0; i < 4; i++) cv[i] = *(const float4*)&s_C[(t0 + i) * 132 + n];
#pragma unroll
            for (int k = 0; k < 4; k++) hv[k] = *(const float4*)&s_hT[(n + k) * 68 + p0];
#pragma unroll
            for (int i = 0; i < 4; i++) {
#pragma unroll
                for (int j = 0; j < 4; j++) {
                    a2[i][j] = fmaf(cv[i].x, ((const float*)&hv[0])[j], a2[i][j]);
                    a2[i][j] = fmaf(cv[i].y, ((const float*)&hv[1])[j], a2[i][j]);
                    a2[i][j] = fmaf(cv[i].z, ((const float*)&hv[2])[j], a2[i][j]);
                    a2[i][j] = fmaf(cv[i].w, ((const float*)&hv[3])[j], a2[i][j]);
                }
            }
        }
#pragma unroll
        for (int i = 0; i < 4; i++) {
            const int t = t0 + i;
            const int row = t0row + t;
            const float et = expf(s_cl[t]);
            float4 xv = *(const float4*)&g_xbc[(size_t)row * CONVDIM + h * HD + p0];
            float4 y4;
            y4.x = fmaf(et, a2[i][0], a1[i][0]) + Dh * xv.x;
            y4.y = fmaf(et, a2[i][1], a1[i][1]) + Dh * xv.y;
            y4.z = fmaf(et, a2[i][2], a1[i][2]) + Dh * xv.z;
            y4.w = fmaf(et, a2[i][3], a1[i][3]) + Dh * xv.w;
            *(float4*)&g_y[(size_t)row * DSSM + h * HD + p0] = y4;
        }
    }
}

// ---------------- gate (silu(z)) + RMSNorm -> fp16 output for GEMM2 ----------------
__global__ __launch_bounds__(256) void gate_rmsnorm_kernel(const float* __restrict__ norm_w)
{
    const int row = blockIdx.x;
    const int tid = threadIdx.x;
    const int w = tid >> 5, lane = tid & 31;

    float vals[8];
    float ss = 0.f;
#pragma unroll
    for (int i = 0; i < 8; i++) {
        int e = i * 256 + tid;
        float z = g_zxbcdt[(size_t)row * DPROJ + e];
        float yv = g_y[(size_t)row * DSSM + e];
        float g = yv * silu_f(z);
        vals[i] = g;
        ss = fmaf(g, g, ss);
    }
    ss += __shfl_xor_sync(0xffffffffu, ss, 16);
    ss += __shfl_xor_sync(0xffffffffu, ss, 8);
    ss += __shfl_xor_sync(0xffffffffu, ss, 4);
    ss += __shfl_xor_sync(0xffffffffu, ss, 2);
    ss += __shfl_xor_sync(0xffffffffu, ss, 1);

    __shared__ float red[8];
    __shared__ float sscale;
    if (lane == 0) red[w] = ss;
    __syncthreads();
    if (tid == 0) {
        float s = 0.f;
#pragma unroll
        for (int k = 0; k < 8; k++) s += red[k];
        sscale = rsqrtf(s / (float)DSSM + EPSV);
    }
    __syncthreads();
    const float scale = sscale;
#pragma unroll
    for (int i = 0; i < 8; i++) {
        int e = i * 256 + tid;
        g_gh[(size_t)row * DSSM + e] = __float2half(vals[i] * scale * norm_w[e]);
    }
}

// ---------------- entry ----------------
extern "C" void kernel_launch(void* const* d_in, const int* in_sizes, int n_in,
                              void* d_out, int out_size)
{
    const float* u       = (const float*)d_in[0];
    const float* W_in    = (const float*)d_in[1];
    const float* conv_w  = (const float*)d_in[2];
    const float* conv_b  = (const float*)d_in[3];
    const float* dt_bias = (const float*)d_in[4];
    const float* A_log   = (const float*)d_in[5];
    const float* Dp      = (const float*)d_in[6];
    const float* norm_w  = (const float*)d_in[7];
    const float* W_out   = (const float*)d_in[8];
    float* out = (float*)d_out;

    float*  zx;  cudaGetSymbolAddress((void**)&zx,  g_zxbcdt);
    __half* uh;  cudaGetSymbolAddress((void**)&uh,  g_uh);
    __half* wih; cudaGetSymbolAddress((void**)&wih, g_Winh);
    __half* gh;  cudaGetSymbolAddress((void**)&gh,  g_gh);
    __half* woh; cudaGetSymbolAddress((void**)&woh, g_Wouth);

    const int smA = (64 * 132 + 64 * 68 + 64 + 64) * 4;
    const int smC = (64 * 132 + 128 * 68 + 128 * 68 + 64 * 68 + 64 * 68 + 64) * 4;
    cudaFuncSetAttribute(ssd_phaseA_kernel, cudaFuncAttributeMaxDynamicSharedMemorySize, smA);
    cudaFuncSetAttribute(ssd_phaseC_kernel, cudaFuncAttributeMaxDynamicSharedMemorySize, smC);

    // 0) fp16 conversions
    {
        size_t nu = (size_t)ROWS * DMODEL;
        f2h_kernel<<<(unsigned)((nu / 4 + 255) / 256), 256>>>(u, uh, nu);
        size_t nw = (size_t)DPROJ * DMODEL;
        f2h_kernel<<<(unsigned)((nw / 4 + 255) / 256), 256>>>(W_in, wih, nw);
        size_t no = (size_t)DMODEL * DSSM;
        f2h_kernel<<<(unsigned)((no / 4 + 255) / 256), 256>>>(W_out, woh, no);
    }
    // 1) in-projection
    {
        dim3 grid((DPROJ + 127) / 128, ROWS / 128);
        hgemm_nt_kernel<<<grid, 256>>>(uh, wih, zx, ROWS, DPROJ, DMODEL);
    }
    // 2) conv + silu
    {
        size_t total = (size_t)ROWS * CONVDIM;
        conv_silu_kernel<<<(unsigned)((total + 255) / 256), 256>>>(conv_w, conv_b);
    }
    // 3) dt softplus + log decay
    dt_kernel<<<(ROWS * NH + 255) / 256, 256>>>(dt_bias, A_log);
    // 4) chunked SSD scan
    ssd_phaseA_kernel<<<NSLOT, 256, smA>>>();
    ssd_phaseB_kernel<<<512, 256>>>();
    ssd_phaseC_kernel<<<NSLOT, 256, smC>>>(Dp);
    // 5) gate + rmsnorm
    gate_rmsnorm_kernel<<<ROWS, 256>>>(norm_w);
    // 6) out-projection
    {
        dim3 grid(DMODEL / 128, ROWS / 128);
        hgemm_nt_kernel<<<grid, 256>>>(gh, woh, out, ROWS, DMODEL, DSSM);
    }
}